// round 5
// baseline (speedup 1.0000x reference)
#include <cuda_runtime.h>
#include <cuda_bf16.h>
#include <cstdint>

#define SLEN 512
#define BB   8
#define HH   16
#define DD   1024
#define WD   64

// Scratch (device globals — no allocation allowed in kernel_launch)
__device__ float g_Q [HH*BB*SLEN*WD];   // [h][b][i][w]
__device__ float g_K [HH*BB*SLEN*WD];
__device__ float g_V [HH*BB*SLEN*WD];
__device__ float g_PK[HH*2*SLEN*WD];    // [h][r][w]
__device__ float g_PQ[HH*2*SLEN*WD];

// ===========================================================================
// mma.sync bf16 helper (sm_80+, compiles for plain sm_100)
// ===========================================================================
__device__ __forceinline__ void mma_bf16(float* d,
    uint32_t a0, uint32_t a1, uint32_t a2, uint32_t a3,
    uint32_t b0, uint32_t b1)
{
    asm volatile(
        "mma.sync.aligned.m16n8k16.row.col.f32.bf16.bf16.f32 "
        "{%0,%1,%2,%3}, {%4,%5,%6,%7}, {%8,%9}, {%0,%1,%2,%3};"
        : "+f"(d[0]), "+f"(d[1]), "+f"(d[2]), "+f"(d[3])
        : "r"(a0), "r"(a1), "r"(a2), "r"(a3), "r"(b0), "r"(b1));
}

__device__ __forceinline__ uint32_t pack_bf16(float a, float b) {
    __nv_bfloat162 h = __floats2bfloat162_rn(a, b);
    return *reinterpret_cast<uint32_t*>(&h);
}
__device__ __forceinline__ float bf16_hi(float a) {
    return __bfloat162float(__float2bfloat16_rn(a));
}

// ===========================================================================
// Fused projection GEMM (round-4, known good):
//   C[5120,3072] = [x(4096); re(1024)] @ [Wq|Wk|Wv]^T  (+bias), scatter store.
// ===========================================================================
#define P_PITCH 20
#define P_ARR   (128*P_PITCH)
#define P_SMEM_WORDS (2*4*P_ARR)
#define P_SMEM_BYTES (P_SMEM_WORDS*4)    // 81920

__global__ __launch_bounds__(256, 1) void proj_mma_kernel(
    const float* __restrict__ x, const float* __restrict__ re,
    const float* __restrict__ Wq, const float* __restrict__ bq,
    const float* __restrict__ Wk, const float* __restrict__ bk,
    const float* __restrict__ Wv, const float* __restrict__ bv,
    float* __restrict__ outQ, float* __restrict__ outK, float* __restrict__ outV,
    float* __restrict__ outPK, float* __restrict__ outPQ)
{
    extern __shared__ uint32_t smw[];
    const int m0 = blockIdx.x * 128;
    const int n0 = blockIdx.y * 128;
    const bool isRe = (m0 >= 4096);
    const int nreg = n0 >> 10;
    if (isRe && nreg == 2) return;

    const int tid  = threadIdx.x;
    const int lane = tid & 31;
    const int wid  = tid >> 5;
    const int wm   = wid >> 2;
    const int wn   = wid & 3;

    const float* Ag = isRe ? (re + (size_t)(m0 - 4096) * DD) : (x + (size_t)m0 * DD);
    const float* Wg = ((nreg == 0) ? Wq : (nreg == 1) ? Wk : Wv) + (size_t)(n0 & 1023) * DD;

    const int srow[4] = { tid >> 3, (tid + 256) >> 3, (tid + 512) >> 3, (tid + 768) >> 3 };
    const int sf4  = tid & 7;

    float acc[4][4][4] = {};
    float4 sa[4], sw4[4];

    #pragma unroll
    for (int j = 0; j < 4; j++) {
        sa[j]  = *(const float4*)(Ag + (size_t)srow[j]*DD + sf4*4);
        sw4[j] = *(const float4*)(Wg + (size_t)srow[j]*DD + sf4*4);
    }
    {
        uint32_t* Ah = smw;             uint32_t* Al = smw + P_ARR;
        uint32_t* Wh = smw + 2*P_ARR;   uint32_t* Wl = smw + 3*P_ARR;
        #pragma unroll
        for (int j = 0; j < 4; j++) {
            int wbase = srow[j]*P_PITCH + sf4*2;
            float4 v = sa[j];
            Ah[wbase]   = pack_bf16(v.x, v.y);
            Ah[wbase+1] = pack_bf16(v.z, v.w);
            Al[wbase]   = pack_bf16(v.x - bf16_hi(v.x), v.y - bf16_hi(v.y));
            Al[wbase+1] = pack_bf16(v.z - bf16_hi(v.z), v.w - bf16_hi(v.w));
            v = sw4[j];
            Wh[wbase]   = pack_bf16(v.x, v.y);
            Wh[wbase+1] = pack_bf16(v.z, v.w);
            Wl[wbase]   = pack_bf16(v.x - bf16_hi(v.x), v.y - bf16_hi(v.y));
            Wl[wbase+1] = pack_bf16(v.z - bf16_hi(v.z), v.w - bf16_hi(v.w));
        }
    }
    __syncthreads();

    for (int c = 0; c < 32; c++) {
        const int buf = c & 1;
        if (c + 1 < 32) {
            const int kc = (c + 1) * 32;
            #pragma unroll
            for (int j = 0; j < 4; j++) {
                sa[j]  = *(const float4*)(Ag + (size_t)srow[j]*DD + kc + sf4*4);
                sw4[j] = *(const float4*)(Wg + (size_t)srow[j]*DD + kc + sf4*4);
            }
        }
        {
            const uint32_t* Ah = smw + (buf*4 + 0)*P_ARR;
            const uint32_t* Al = smw + (buf*4 + 1)*P_ARR;
            const uint32_t* Wh = smw + (buf*4 + 2)*P_ARR;
            const uint32_t* Wl = smw + (buf*4 + 3)*P_ARR;
            #pragma unroll
            for (int ks = 0; ks < 2; ks++) {
                const int kw = (lane & 3) + ks*8;
                uint32_t ah[4][4], al[4][4];
                #pragma unroll
                for (int mt = 0; mt < 4; mt++) {
                    int r = wm*64 + mt*16 + (lane >> 2);
                    int b0 = r*P_PITCH + kw;
                    ah[mt][0] = Ah[b0];       ah[mt][1] = Ah[b0 + 8*P_PITCH];
                    ah[mt][2] = Ah[b0 + 4];   ah[mt][3] = Ah[b0 + 8*P_PITCH + 4];
                    al[mt][0] = Al[b0];       al[mt][1] = Al[b0 + 8*P_PITCH];
                    al[mt][2] = Al[b0 + 4];   al[mt][3] = Al[b0 + 8*P_PITCH + 4];
                }
                uint32_t bh[4][2], bl[4][2];
                #pragma unroll
                for (int nt = 0; nt < 4; nt++) {
                    int rn = wn*32 + nt*8 + (lane >> 2);
                    int b0 = rn*P_PITCH + kw;
                    bh[nt][0] = Wh[b0]; bh[nt][1] = Wh[b0 + 4];
                    bl[nt][0] = Wl[b0]; bl[nt][1] = Wl[b0 + 4];
                }
                #pragma unroll
                for (int mt = 0; mt < 4; mt++)
                    #pragma unroll
                    for (int nt = 0; nt < 4; nt++) {
                        mma_bf16(acc[mt][nt], ah[mt][0], ah[mt][1], ah[mt][2], ah[mt][3],
                                 bh[nt][0], bh[nt][1]);
                        mma_bf16(acc[mt][nt], ah[mt][0], ah[mt][1], ah[mt][2], ah[mt][3],
                                 bl[nt][0], bl[nt][1]);
                        mma_bf16(acc[mt][nt], al[mt][0], al[mt][1], al[mt][2], al[mt][3],
                                 bh[nt][0], bh[nt][1]);
                    }
            }
        }
        if (c + 1 < 32) {
            const int ob = 1 - buf;
            uint32_t* Ah = smw + (ob*4 + 0)*P_ARR;
            uint32_t* Al = smw + (ob*4 + 1)*P_ARR;
            uint32_t* Wh = smw + (ob*4 + 2)*P_ARR;
            uint32_t* Wl = smw + (ob*4 + 3)*P_ARR;
            #pragma unroll
            for (int j = 0; j < 4; j++) {
                int wbase = srow[j]*P_PITCH + sf4*2;
                float4 v = sa[j];
                Ah[wbase]   = pack_bf16(v.x, v.y);
                Ah[wbase+1] = pack_bf16(v.z, v.w);
                Al[wbase]   = pack_bf16(v.x - bf16_hi(v.x), v.y - bf16_hi(v.y));
                Al[wbase+1] = pack_bf16(v.z - bf16_hi(v.z), v.w - bf16_hi(v.w));
                v = sw4[j];
                Wh[wbase]   = pack_bf16(v.x, v.y);
                Wh[wbase+1] = pack_bf16(v.z, v.w);
                Wl[wbase]   = pack_bf16(v.x - bf16_hi(v.x), v.y - bf16_hi(v.y));
                Wl[wbase+1] = pack_bf16(v.z - bf16_hi(v.z), v.w - bf16_hi(v.w));
            }
        }
        __syncthreads();
    }

    const float* bp = (nreg == 0) ? bq : (nreg == 1) ? bk : bv;
    float* baseO;
    int Mrows, moff;
    if (!isRe) {
        baseO = (nreg == 0) ? outQ : (nreg == 1) ? outK : outV;
        Mrows = 4096; moff = m0;
    } else {
        baseO = (nreg == 0) ? outPQ : outPK;
        Mrows = 1024; moff = m0 - 4096;
    }

    #pragma unroll
    for (int mt = 0; mt < 4; mt++) {
        int m = moff + wm*64 + mt*16 + (lane >> 2);
        #pragma unroll
        for (int nt = 0; nt < 4; nt++) {
            int ncl = (n0 & 1023) + wn*32 + nt*8 + (lane & 3)*2;
            int hh = ncl >> 6, w = ncl & 63;
            float bx = bp[ncl], by = bp[ncl + 1];
            float* d0 = baseO + ((size_t)hh*Mrows + m)*64 + w;
            float2 v0 = { acc[mt][nt][0] + bx, acc[mt][nt][1] + by };
            float2 v1 = { acc[mt][nt][2] + bx, acc[mt][nt][3] + by };
            *(float2*)d0 = v0;
            *(float2*)(d0 + 8*64) = v1;
        }
    }
}

// ===========================================================================
// Fused disentangled flash attention v3 — diagonal thread mapping.
// CTA: 128 i-rows (two 64-row groups), Bj=64, 512 threads.
// Score phase: thread (G, a, g) owns rows 64G+4a.., cols 4((a+g)&15)..
//   -> band index depends only on (G,g,wrap): broadcast smem loads.
// Softmax/PV: row-major (ty, tx) mapping via smem Ss tile (aliased on PKT).
// ===========================================================================
#define QP 132
#define KP 68
#define VP 68
#define BP 200
#define SP 68
#define OFF_QST 0
#define OFF_KST (OFF_QST + 64*QP)      // 8448
#define OFF_VS  (OFF_KST + 64*KP)      // 12800
#define OFF_PKT (OFF_VS  + 64*VP)      // 17152
#define OFF_PQT (OFF_PKT + 64*BP)      // 29952
#define ATTN_SMEM_FLOATS (OFF_PQT + 64*BP)   // 42752
#define ATTN_SMEM_BYTES  (ATTN_SMEM_FLOATS * 4)  // 171008

__global__ __launch_bounds__(512, 1) void attn_kernel(float* __restrict__ out)
{
    extern __shared__ float sm[];
    float* QsT = sm + OFF_QST;     // [w][i]  pitch QP
    float* KsT = sm + OFF_KST;     // [w][j]  pitch KP
    float* Vs  = sm + OFF_VS;      // [j][w]  pitch VP
    float* PKT = sm + OFF_PKT;     // [w][t]  pitch BP (192 t-rows)
    float* PQT = sm + OFF_PQT;     // [w][t]  pitch BP
    float* Ss  = sm + OFF_PKT;     // [i][j]  pitch SP (ALIASED over PKT)

    const int h  = blockIdx.z;
    const int b  = blockIdx.y;
    const int i0 = blockIdx.x * 128;
    const int tid = threadIdx.x;

    // score-phase mapping
    const int G  = tid >> 8;                 // 0..1 (i-row group)
    const int a  = tid & 15;                 // row block within group
    const int g  = (tid >> 4) & 15;          // diagonal offset
    const int cg = (a + g) & 15;             // col block
    const int tb = 64*G + 60 - 4*g + (((a + g) >= 16) ? 64 : 0);  // band window base

    // softmax/PV mapping
    const int ty = tid >> 4;                 // 0..31 -> rows 4ty..
    const int tx = tid & 15;                 // cols 4tx..

    const float* Qg  = g_Q  + ((size_t)(h*BB + b)*SLEN + i0)*WD;
    const float* Kg  = g_K  + (size_t)(h*BB + b)*SLEN*WD;
    const float* Vg  = g_V  + (size_t)(h*BB + b)*SLEN*WD;
    const float* PKg = g_PK + (size_t)h*2*SLEN*WD;
    const float* PQg = g_PQ + (size_t)h*2*SLEN*WD;

    // Stage Q transposed [w][i] (once). Lanes vary row -> conflict-free STS.
    for (int idx = tid; idx < 128*16; idx += 512) {
        int r = idx & 127, cc = (idx >> 7) << 2;
        float4 v = *(const float4*)(Qg + r*WD + cc);
        QsT[(cc+0)*QP + r] = v.x; QsT[(cc+1)*QP + r] = v.y;
        QsT[(cc+2)*QP + r] = v.z; QsT[(cc+3)*QP + r] = v.w;
    }

    float m_i[4], l_i[4], o[4][4];
    #pragma unroll
    for (int r = 0; r < 4; r++) {
        m_i[r] = -1e30f; l_i[r] = 0.f;
        #pragma unroll
        for (int c = 0; c < 4; c++) o[r][c] = 0.f;
    }

    const float scale = rsqrtf(192.0f);   // 1/sqrt(64*3)

    for (int jt = 0; jt < 8; jt++) {
        const int j0 = jt * 64;
        const int r0 = i0 - j0 + 448;     // absolute band start (rows r0..r0+191)
        __syncthreads();                  // prior PV reads of Vs/Ps complete

        // K transposed [w][j]: lanes vary row -> conflict-free STS
        for (int idx = tid; idx < 64*16; idx += 512) {
            int r = idx & 63, cc = (idx >> 6) << 2;
            float4 kv = *(const float4*)(Kg + (j0 + r)*WD + cc);
            KsT[(cc+0)*KP + r] = kv.x; KsT[(cc+1)*KP + r] = kv.y;
            KsT[(cc+2)*KP + r] = kv.z; KsT[(cc+3)*KP + r] = kv.w;
        }
        // V row-major [j][w]: coalesced
        for (int idx = tid; idx < 64*16; idx += 512) {
            int r = idx >> 4, cc = (idx & 15) << 2;
            *(float4*)(Vs + r*VP + cc) = *(const float4*)(Vg + (j0 + r)*WD + cc);
        }
        // Bands transposed [w][t], 192 t-rows: lanes vary t -> conflict-free STS
        for (int idx = tid; idx < 192*16; idx += 512) {
            int t = idx % 192, cc = (idx / 192) << 2;
            float4 pv4 = *(const float4*)(PKg + (size_t)(r0 + t)*WD + cc);
            PKT[(cc+0)*BP + t] = pv4.x; PKT[(cc+1)*BP + t] = pv4.y;
            PKT[(cc+2)*BP + t] = pv4.z; PKT[(cc+3)*BP + t] = pv4.w;
            float4 qv4 = *(const float4*)(PQg + (size_t)(r0 + t)*WD + cc);
            PQT[(cc+0)*BP + t] = qv4.x; PQT[(cc+1)*BP + t] = qv4.y;
            PQT[(cc+2)*BP + t] = qv4.z; PQT[(cc+3)*BP + t] = qv4.w;
        }
        __syncthreads();

        // Score tile (diagonal mapping): band loads broadcast across half-warp
        float s[4][4] = {};
        #pragma unroll 4
        for (int w = 0; w < 64; w++) {
            float4 qa4 = *(const float4*)(QsT + w*QP + 64*G + 4*a);
            float4 ka4 = *(const float4*)(KsT + w*KP + 4*cg);
            float4 pk0 = *(const float4*)(PKT + w*BP + tb);
            float4 pk1 = *(const float4*)(PKT + w*BP + tb + 4);
            float4 pq0 = *(const float4*)(PQT + w*BP + tb);
            float4 pq1 = *(const float4*)(PQT + w*BP + tb + 4);
            float q[4]  = {qa4.x, qa4.y, qa4.z, qa4.w};
            float k[4]  = {ka4.x, ka4.y, ka4.z, ka4.w};
            float pk[8] = {pk0.x, pk0.y, pk0.z, pk0.w, pk1.x, pk1.y, pk1.z, pk1.w};
            float pq[8] = {pq0.x, pq0.y, pq0.z, pq0.w, pq1.x, pq1.y, pq1.z, pq1.w};
            #pragma unroll
            for (int ri = 0; ri < 4; ri++)
                #pragma unroll
                for (int rj = 0; rj < 4; rj++) {
                    const int d = ri - rj + 3;   // constant after unroll
                    s[ri][rj] += q[ri]*k[rj] + q[ri]*pk[d] + k[rj]*pq[d];
                }
        }

        __syncthreads();   // all band reads done before Ss (aliased) is written

        #pragma unroll
        for (int ri = 0; ri < 4; ri++) {
            float4 sv = { s[ri][0]*scale, s[ri][1]*scale, s[ri][2]*scale, s[ri][3]*scale };
            *(float4*)(Ss + (64*G + 4*a + ri)*SP + 4*cg) = sv;
        }
        __syncthreads();

        // Online softmax (row-major mapping; row shared by 16 tx lanes)
        #pragma unroll
        for (int ri = 0; ri < 4; ri++) {
            float4 sv = *(const float4*)(Ss + (4*ty + ri)*SP + 4*tx);
            float mx = fmaxf(fmaxf(sv.x, sv.y), fmaxf(sv.z, sv.w));
            #pragma unroll
            for (int off = 8; off > 0; off >>= 1)
                mx = fmaxf(mx, __shfl_xor_sync(0xffffffffu, mx, off));
            float mnew = fmaxf(m_i[ri], mx);
            float corr = __expf(m_i[ri] - mnew);
            float p0 = __expf(sv.x - mnew);
            float p1 = __expf(sv.y - mnew);
            float p2 = __expf(sv.z - mnew);
            float p3 = __expf(sv.w - mnew);
            float rs = p0 + p1 + p2 + p3;
            #pragma unroll
            for (int off = 8; off > 0; off >>= 1)
                rs += __shfl_xor_sync(0xffffffffu, rs, off);
            l_i[ri] = l_i[ri]*corr + rs;
            m_i[ri] = mnew;
            #pragma unroll
            for (int rw = 0; rw < 4; rw++) o[ri][rw] *= corr;
            float4 pv = {p0, p1, p2, p3};
            *(float4*)(Ss + (4*ty + ri)*SP + 4*tx) = pv;
        }
        __syncthreads();

        // O += P @ V
        #pragma unroll 4
        for (int j = 0; j < 64; j++) {
            float4 vv = *(const float4*)(Vs + j*VP + 4*tx);
            float va[4] = {vv.x, vv.y, vv.z, vv.w};
            float pa[4];
            #pragma unroll
            for (int ri = 0; ri < 4; ri++) pa[ri] = Ss[(4*ty + ri)*SP + j];
            #pragma unroll
            for (int ri = 0; ri < 4; ri++)
                #pragma unroll
                for (int rw = 0; rw < 4; rw++)
                    o[ri][rw] += pa[ri] * va[rw];
        }
    }

    // Write output: out[b][i][h*64 + w]
    #pragma unroll
    for (int ri = 0; ri < 4; ri++) {
        int i = i0 + 4*ty + ri;
        float inv = 1.0f / l_i[ri];
        float4 ov = { o[ri][0]*inv, o[ri][1]*inv, o[ri][2]*inv, o[ri][3]*inv };
        *(float4*)(out + ((size_t)b*SLEN + i)*DD + h*64 + 4*tx) = ov;
    }
}

// ===========================================================================
// Launch
// ===========================================================================
extern "C" void kernel_launch(void* const* d_in, const int* in_sizes, int n_in,
                              void* d_out, int out_size)
{
    (void)in_sizes; (void)n_in; (void)out_size;
    const float* x  = (const float*)d_in[0];
    const float* re = (const float*)d_in[1];
    const float* Wq = (const float*)d_in[2];
    const float* bq = (const float*)d_in[3];
    const float* Wk = (const float*)d_in[4];
    const float* bk = (const float*)d_in[5];
    const float* Wv = (const float*)d_in[6];
    const float* bv = (const float*)d_in[7];
    float* out = (float*)d_out;

    void *qp, *kp, *vp, *pkp, *pqp;
    cudaGetSymbolAddress(&qp,  g_Q);
    cudaGetSymbolAddress(&kp,  g_K);
    cudaGetSymbolAddress(&vp,  g_V);
    cudaGetSymbolAddress(&pkp, g_PK);
    cudaGetSymbolAddress(&pqp, g_PQ);

    cudaFuncSetAttribute(proj_mma_kernel, cudaFuncAttributeMaxDynamicSharedMemorySize,
                         P_SMEM_BYTES);
    cudaFuncSetAttribute(attn_kernel, cudaFuncAttributeMaxDynamicSharedMemorySize,
                         ATTN_SMEM_BYTES);

    proj_mma_kernel<<<dim3(40, 24), dim3(256), P_SMEM_BYTES>>>(
        x, re, Wq, bq, Wk, bk, Wv, bv,
        (float*)qp, (float*)kp, (float*)vp, (float*)pkp, (float*)pqp);

    attn_kernel<<<dim3(4, BB, HH), dim3(512), ATTN_SMEM_BYTES>>>(out);
}

// round 6
// speedup vs baseline: 1.0617x; 1.0617x over previous
#include <cuda_runtime.h>
#include <cuda_bf16.h>
#include <cstdint>

#define SLEN 512
#define BB   8
#define HH   16
#define DD   1024
#define WD   64

// Scratch (device globals — no allocation allowed in kernel_launch)
__device__ float g_Q [HH*BB*SLEN*WD];   // [h][m=b*512+i][w]
__device__ float g_K [HH*BB*SLEN*WD];
__device__ float g_V [HH*BB*SLEN*WD];
__device__ float g_PK[HH*2*SLEN*WD];    // [h][r][w]
__device__ float g_PQ[HH*2*SLEN*WD];
// Bias tables: [h][m(4096)][r(1024)]
__device__ float g_C2P[(size_t)HH*4096*1024];
__device__ float g_P2C[(size_t)HH*4096*1024];

// ===========================================================================
// mma.sync bf16 helpers (sm_80+, compiles for plain sm_100)
// ===========================================================================
__device__ __forceinline__ void mma_bf16(float* d,
    uint32_t a0, uint32_t a1, uint32_t a2, uint32_t a3,
    uint32_t b0, uint32_t b1)
{
    asm volatile(
        "mma.sync.aligned.m16n8k16.row.col.f32.bf16.bf16.f32 "
        "{%0,%1,%2,%3}, {%4,%5,%6,%7}, {%8,%9}, {%0,%1,%2,%3};"
        : "+f"(d[0]), "+f"(d[1]), "+f"(d[2]), "+f"(d[3])
        : "r"(a0), "r"(a1), "r"(a2), "r"(a3), "r"(b0), "r"(b1));
}
__device__ __forceinline__ uint32_t pack_bf16(float a, float b) {
    __nv_bfloat162 h = __floats2bfloat162_rn(a, b);
    return *reinterpret_cast<uint32_t*>(&h);
}
__device__ __forceinline__ float bf16_hi(float a) {
    return __bfloat162float(__float2bfloat16_rn(a));
}

// ===========================================================================
// Fused projection GEMM (round-4, known good):
//   C[5120,3072] = [x(4096); re(1024)] @ [Wq|Wk|Wv]^T  (+bias), scatter store.
// ===========================================================================
#define P_PITCH 20
#define P_ARR   (128*P_PITCH)
#define P_SMEM_WORDS (2*4*P_ARR)
#define P_SMEM_BYTES (P_SMEM_WORDS*4)    // 81920

__global__ __launch_bounds__(256, 1) void proj_mma_kernel(
    const float* __restrict__ x, const float* __restrict__ re,
    const float* __restrict__ Wq, const float* __restrict__ bq,
    const float* __restrict__ Wk, const float* __restrict__ bk,
    const float* __restrict__ Wv, const float* __restrict__ bv,
    float* __restrict__ outQ, float* __restrict__ outK, float* __restrict__ outV,
    float* __restrict__ outPK, float* __restrict__ outPQ)
{
    extern __shared__ uint32_t smw[];
    const int m0 = blockIdx.x * 128;
    const int n0 = blockIdx.y * 128;
    const bool isRe = (m0 >= 4096);
    const int nreg = n0 >> 10;
    if (isRe && nreg == 2) return;

    const int tid  = threadIdx.x;
    const int lane = tid & 31;
    const int wid  = tid >> 5;
    const int wm   = wid >> 2;
    const int wn   = wid & 3;

    const float* Ag = isRe ? (re + (size_t)(m0 - 4096) * DD) : (x + (size_t)m0 * DD);
    const float* Wg = ((nreg == 0) ? Wq : (nreg == 1) ? Wk : Wv) + (size_t)(n0 & 1023) * DD;

    const int srow[4] = { tid >> 3, (tid + 256) >> 3, (tid + 512) >> 3, (tid + 768) >> 3 };
    const int sf4  = tid & 7;

    float acc[4][4][4] = {};
    float4 sa[4], sw4[4];

    #pragma unroll
    for (int j = 0; j < 4; j++) {
        sa[j]  = *(const float4*)(Ag + (size_t)srow[j]*DD + sf4*4);
        sw4[j] = *(const float4*)(Wg + (size_t)srow[j]*DD + sf4*4);
    }
    {
        uint32_t* Ah = smw;             uint32_t* Al = smw + P_ARR;
        uint32_t* Wh = smw + 2*P_ARR;   uint32_t* Wl = smw + 3*P_ARR;
        #pragma unroll
        for (int j = 0; j < 4; j++) {
            int wbase = srow[j]*P_PITCH + sf4*2;
            float4 v = sa[j];
            Ah[wbase]   = pack_bf16(v.x, v.y);
            Ah[wbase+1] = pack_bf16(v.z, v.w);
            Al[wbase]   = pack_bf16(v.x - bf16_hi(v.x), v.y - bf16_hi(v.y));
            Al[wbase+1] = pack_bf16(v.z - bf16_hi(v.z), v.w - bf16_hi(v.w));
            v = sw4[j];
            Wh[wbase]   = pack_bf16(v.x, v.y);
            Wh[wbase+1] = pack_bf16(v.z, v.w);
            Wl[wbase]   = pack_bf16(v.x - bf16_hi(v.x), v.y - bf16_hi(v.y));
            Wl[wbase+1] = pack_bf16(v.z - bf16_hi(v.z), v.w - bf16_hi(v.w));
        }
    }
    __syncthreads();

    for (int c = 0; c < 32; c++) {
        const int buf = c & 1;
        if (c + 1 < 32) {
            const int kc = (c + 1) * 32;
            #pragma unroll
            for (int j = 0; j < 4; j++) {
                sa[j]  = *(const float4*)(Ag + (size_t)srow[j]*DD + kc + sf4*4);
                sw4[j] = *(const float4*)(Wg + (size_t)srow[j]*DD + kc + sf4*4);
            }
        }
        {
            const uint32_t* Ah = smw + (buf*4 + 0)*P_ARR;
            const uint32_t* Al = smw + (buf*4 + 1)*P_ARR;
            const uint32_t* Wh = smw + (buf*4 + 2)*P_ARR;
            const uint32_t* Wl = smw + (buf*4 + 3)*P_ARR;
            #pragma unroll
            for (int ks = 0; ks < 2; ks++) {
                const int kw = (lane & 3) + ks*8;
                uint32_t ah[4][4], al[4][4];
                #pragma unroll
                for (int mt = 0; mt < 4; mt++) {
                    int r = wm*64 + mt*16 + (lane >> 2);
                    int b0 = r*P_PITCH + kw;
                    ah[mt][0] = Ah[b0];       ah[mt][1] = Ah[b0 + 8*P_PITCH];
                    ah[mt][2] = Ah[b0 + 4];   ah[mt][3] = Ah[b0 + 8*P_PITCH + 4];
                    al[mt][0] = Al[b0];       al[mt][1] = Al[b0 + 8*P_PITCH];
                    al[mt][2] = Al[b0 + 4];   al[mt][3] = Al[b0 + 8*P_PITCH + 4];
                }
                uint32_t bh[4][2], bl[4][2];
                #pragma unroll
                for (int nt = 0; nt < 4; nt++) {
                    int rn = wn*32 + nt*8 + (lane >> 2);
                    int b0 = rn*P_PITCH + kw;
                    bh[nt][0] = Wh[b0]; bh[nt][1] = Wh[b0 + 4];
                    bl[nt][0] = Wl[b0]; bl[nt][1] = Wl[b0 + 4];
                }
                #pragma unroll
                for (int mt = 0; mt < 4; mt++)
                    #pragma unroll
                    for (int nt = 0; nt < 4; nt++) {
                        mma_bf16(acc[mt][nt], ah[mt][0], ah[mt][1], ah[mt][2], ah[mt][3],
                                 bh[nt][0], bh[nt][1]);
                        mma_bf16(acc[mt][nt], ah[mt][0], ah[mt][1], ah[mt][2], ah[mt][3],
                                 bl[nt][0], bl[nt][1]);
                        mma_bf16(acc[mt][nt], al[mt][0], al[mt][1], al[mt][2], al[mt][3],
                                 bh[nt][0], bh[nt][1]);
                    }
            }
        }
        if (c + 1 < 32) {
            const int ob = 1 - buf;
            uint32_t* Ah = smw + (ob*4 + 0)*P_ARR;
            uint32_t* Al = smw + (ob*4 + 1)*P_ARR;
            uint32_t* Wh = smw + (ob*4 + 2)*P_ARR;
            uint32_t* Wl = smw + (ob*4 + 3)*P_ARR;
            #pragma unroll
            for (int j = 0; j < 4; j++) {
                int wbase = srow[j]*P_PITCH + sf4*2;
                float4 v = sa[j];
                Ah[wbase]   = pack_bf16(v.x, v.y);
                Ah[wbase+1] = pack_bf16(v.z, v.w);
                Al[wbase]   = pack_bf16(v.x - bf16_hi(v.x), v.y - bf16_hi(v.y));
                Al[wbase+1] = pack_bf16(v.z - bf16_hi(v.z), v.w - bf16_hi(v.w));
                v = sw4[j];
                Wh[wbase]   = pack_bf16(v.x, v.y);
                Wh[wbase+1] = pack_bf16(v.z, v.w);
                Wl[wbase]   = pack_bf16(v.x - bf16_hi(v.x), v.y - bf16_hi(v.y));
                Wl[wbase+1] = pack_bf16(v.z - bf16_hi(v.z), v.w - bf16_hi(v.w));
            }
        }
        __syncthreads();
    }

    const float* bp = (nreg == 0) ? bq : (nreg == 1) ? bk : bv;
    float* baseO;
    int Mrows, moff;
    if (!isRe) {
        baseO = (nreg == 0) ? outQ : (nreg == 1) ? outK : outV;
        Mrows = 4096; moff = m0;
    } else {
        baseO = (nreg == 0) ? outPQ : outPK;
        Mrows = 1024; moff = m0 - 4096;
    }

    #pragma unroll
    for (int mt = 0; mt < 4; mt++) {
        int m = moff + wm*64 + mt*16 + (lane >> 2);
        #pragma unroll
        for (int nt = 0; nt < 4; nt++) {
            int ncl = (n0 & 1023) + wn*32 + nt*8 + (lane & 3)*2;
            int hh = ncl >> 6, w = ncl & 63;
            float bx = bp[ncl], by = bp[ncl + 1];
            float* d0 = baseO + ((size_t)hh*Mrows + m)*64 + w;
            float2 v0 = { acc[mt][nt][0] + bx, acc[mt][nt][1] + by };
            float2 v1 = { acc[mt][nt][2] + bx, acc[mt][nt][3] + by };
            *(float2*)d0 = v0;
            *(float2*)(d0 + 8*64) = v1;
        }
    }
}

// ===========================================================================
// Bias table GEMM (split-bf16 HMMA):
//   z = h + 16*tbl.  tbl 0: C2P[h,m,r] = Q[h,m,:]·PK[h,r,:]
//                    tbl 1: P2C[h,m,r] = K[h,m,:]·PQ[h,r,:]
// 128x128 tile, K=64 (4 k-steps), 256 threads, same fragment scheme as proj.
// ===========================================================================
#define T_PITCH 36
#define T_ARR   (128*T_PITCH)            // 4608 words
#define T_SMEM_BYTES (4*T_ARR*4)         // 73728

__global__ __launch_bounds__(256, 1) void bias_table_kernel()
{
    extern __shared__ uint32_t smw[];
    const int m0 = blockIdx.x * 128;     // [0,4096)
    const int n0 = blockIdx.y * 128;     // [0,1024)
    const int h   = blockIdx.z & 15;
    const int tbl = blockIdx.z >> 4;

    const int tid  = threadIdx.x;
    const int lane = tid & 31;
    const int wid  = tid >> 5;
    const int wm   = wid >> 2;
    const int wn   = wid & 3;

    const float* Ag = (tbl ? g_K : g_Q) + ((size_t)h*4096 + m0) * WD;
    const float* Bg = (tbl ? g_PQ : g_PK) + ((size_t)h*1024 + n0) * WD;
    float* Cg = (tbl ? g_P2C : g_C2P) + (size_t)h*4096*1024;

    uint32_t* Ah = smw;             uint32_t* Al = smw + T_ARR;
    uint32_t* Bh = smw + 2*T_ARR;   uint32_t* Bl = smw + 3*T_ARR;

    // Stage full K=64 as hi/lo bf16
    #pragma unroll
    for (int v = 0; v < 8; v++) {
        int idx = v*256 + tid;           // 0..2047
        int row = idx >> 4;
        int cw  = idx & 15;              // float4 index within 64-col row
        int wbase = row*T_PITCH + cw*2;
        float4 a = *(const float4*)(Ag + (size_t)row*WD + cw*4);
        Ah[wbase]   = pack_bf16(a.x, a.y);
        Ah[wbase+1] = pack_bf16(a.z, a.w);
        Al[wbase]   = pack_bf16(a.x - bf16_hi(a.x), a.y - bf16_hi(a.y));
        Al[wbase+1] = pack_bf16(a.z - bf16_hi(a.z), a.w - bf16_hi(a.w));
        float4 b = *(const float4*)(Bg + (size_t)row*WD + cw*4);
        Bh[wbase]   = pack_bf16(b.x, b.y);
        Bh[wbase+1] = pack_bf16(b.z, b.w);
        Bl[wbase]   = pack_bf16(b.x - bf16_hi(b.x), b.y - bf16_hi(b.y));
        Bl[wbase+1] = pack_bf16(b.z - bf16_hi(b.z), b.w - bf16_hi(b.w));
    }
    __syncthreads();

    float acc[4][4][4] = {};
    #pragma unroll
    for (int ks = 0; ks < 4; ks++) {
        const int kw = (lane & 3) + ks*8;
        uint32_t ah[4][4], al[4][4];
        #pragma unroll
        for (int mt = 0; mt < 4; mt++) {
            int r = wm*64 + mt*16 + (lane >> 2);
            int b0 = r*T_PITCH + kw;
            ah[mt][0] = Ah[b0];       ah[mt][1] = Ah[b0 + 8*T_PITCH];
            ah[mt][2] = Ah[b0 + 4];   ah[mt][3] = Ah[b0 + 8*T_PITCH + 4];
            al[mt][0] = Al[b0];       al[mt][1] = Al[b0 + 8*T_PITCH];
            al[mt][2] = Al[b0 + 4];   al[mt][3] = Al[b0 + 8*T_PITCH + 4];
        }
        uint32_t bh[4][2], bl[4][2];
        #pragma unroll
        for (int nt = 0; nt < 4; nt++) {
            int rn = wn*32 + nt*8 + (lane >> 2);
            int b0 = rn*T_PITCH + kw;
            bh[nt][0] = Bh[b0]; bh[nt][1] = Bh[b0 + 4];
            bl[nt][0] = Bl[b0]; bl[nt][1] = Bl[b0 + 4];
        }
        #pragma unroll
        for (int mt = 0; mt < 4; mt++)
            #pragma unroll
            for (int nt = 0; nt < 4; nt++) {
                mma_bf16(acc[mt][nt], ah[mt][0], ah[mt][1], ah[mt][2], ah[mt][3],
                         bh[nt][0], bh[nt][1]);
                mma_bf16(acc[mt][nt], ah[mt][0], ah[mt][1], ah[mt][2], ah[mt][3],
                         bl[nt][0], bl[nt][1]);
                mma_bf16(acc[mt][nt], al[mt][0], al[mt][1], al[mt][2], al[mt][3],
                         bh[nt][0], bh[nt][1]);
            }
    }

    // Row-major store
    #pragma unroll
    for (int mt = 0; mt < 4; mt++) {
        int m = m0 + wm*64 + mt*16 + (lane >> 2);
        #pragma unroll
        for (int nt = 0; nt < 4; nt++) {
            int ncl = n0 + wn*32 + nt*8 + (lane & 3)*2;
            float* d0 = Cg + (size_t)m*1024 + ncl;
            *(float2*)d0 = make_float2(acc[mt][nt][0], acc[mt][nt][1]);
            *(float2*)(d0 + 8*1024) = make_float2(acc[mt][nt][2], acc[mt][nt][3]);
        }
    }
}

// ===========================================================================
// Fused flash attention with precomputed bias tables.
// CTA: 128 i-rows x 64 j-cols per tile, 512 threads, round-4 (ty,tx) mapping.
// Inner loop is pure QK^T; biases gathered per-tile from g_C2P/g_P2C.
// ===========================================================================
#define QP 132
#define KP 68
#define VP 68
#define CP 68      // C2Ps pitch ([di][jl])
#define PP 129     // P2Cs pitch ([jl][di])
#define SP 68
#define OFF_KST (64*QP)                 // 8448
#define OFF_VS  (OFF_KST + 64*KP)       // 12800
#define OFF_C2P (OFF_VS + 64*VP)        // 17152
#define OFF_P2C (OFF_C2P + 128*CP)      // 25856
#define OFF_SS  (OFF_P2C + 64*PP)       // 34112
#define ATTN_SMEM_FLOATS (OFF_SS + 128*SP)  // 42816
#define ATTN_SMEM_BYTES  (ATTN_SMEM_FLOATS * 4)  // 171264

__global__ __launch_bounds__(512, 1) void attn_kernel(float* __restrict__ out)
{
    extern __shared__ float sm[];
    float* QsT  = sm;                // [w][i]   pitch QP
    float* KsT  = sm + OFF_KST;      // [w][j]   pitch KP
    float* Vs   = sm + OFF_VS;       // [j][w]   pitch VP
    float* C2Ps = sm + OFF_C2P;      // [di][jl] pitch CP
    float* P2Cs = sm + OFF_P2C;      // [jl][di] pitch PP
    float* Ss   = sm + OFF_SS;       // [di][jl] pitch SP (P matrix)

    const int h  = blockIdx.z;
    const int b  = blockIdx.y;
    const int i0 = blockIdx.x * 128;
    const int tid = threadIdx.x;
    const int ty = tid >> 4;         // 0..31 -> rows 4ty..
    const int tx = tid & 15;         // cols 4tx..

    const float* Qg  = g_Q  + ((size_t)(h*BB + b)*SLEN + i0)*WD;
    const float* Kg  = g_K  + (size_t)(h*BB + b)*SLEN*WD;
    const float* Vg  = g_V  + (size_t)(h*BB + b)*SLEN*WD;
    const float* C2Pg = g_C2P + ((size_t)h*4096 + (size_t)b*512)*1024;
    const float* P2Cg = g_P2C + ((size_t)h*4096 + (size_t)b*512)*1024;

    // Stage Q transposed [w][i] once (conflict-free STS: lanes vary row)
    for (int t = tid; t < 128*16; t += 512) {
        int r = t & 127, cc = (t >> 7) << 2;
        float4 v = *(const float4*)(Qg + r*WD + cc);
        QsT[(cc+0)*QP + r] = v.x; QsT[(cc+1)*QP + r] = v.y;
        QsT[(cc+2)*QP + r] = v.z; QsT[(cc+3)*QP + r] = v.w;
    }

    float m_i[4], l_i[4], o[4][4];
    #pragma unroll
    for (int r = 0; r < 4; r++) {
        m_i[r] = -1e30f; l_i[r] = 0.f;
        #pragma unroll
        for (int c = 0; c < 4; c++) o[r][c] = 0.f;
    }

    const float scale = rsqrtf(192.0f);   // 1/sqrt(64*3)

    for (int jt = 0; jt < 8; jt++) {
        const int j0 = jt * 64;
        __syncthreads();                  // prior tile's Vs/Ss reads complete

        // K transposed [w][j]
        for (int t = tid; t < 64*16; t += 512) {
            int r = t & 63, cc = (t >> 6) << 2;
            float4 kv = *(const float4*)(Kg + (j0 + r)*WD + cc);
            KsT[(cc+0)*KP + r] = kv.x; KsT[(cc+1)*KP + r] = kv.y;
            KsT[(cc+2)*KP + r] = kv.z; KsT[(cc+3)*KP + r] = kv.w;
        }
        // V row-major [j][w]
        for (int t = tid; t < 64*16; t += 512) {
            int r = t >> 4, cc = (t & 15) << 2;
            *(float4*)(Vs + r*VP + cc) = *(const float4*)(Vg + (j0 + r)*WD + cc);
        }
        // C2P gather: C2Ps[di][jl] = C2Pg[i0+di][ (i0+di) - (j0+jl) + 511 ]
        for (int t = tid; t < 2048; t += 512) {
            int di = t >> 4, jg = t & 15;
            const float* src = C2Pg + ((size_t)(i0 + di))*1024
                               + (i0 + di) - j0 + 511 - 4*jg;
            float4 v = { src[0], src[-1], src[-2], src[-3] };
            *(float4*)(C2Ps + di*CP + 4*jg) = v;
        }
        // P2C gather: P2Cs[jl][di] = P2Cg[j0+jl][ (i0+di) - (j0+jl) + 511 ]
        for (int t = tid; t < 8192; t += 512) {
            int jl = t >> 7, di = t & 127;
            const float* src = P2Cg + ((size_t)(j0 + jl))*1024
                               + i0 - j0 - jl + 511;
            P2Cs[jl*PP + di] = src[di];
        }
        __syncthreads();

        // Score tile: pure QK^T
        float s[4][4] = {};
        #pragma unroll 4
        for (int w = 0; w < 64; w++) {
            float4 qa4 = *(const float4*)(QsT + w*QP + 4*ty);
            float4 ka4 = *(const float4*)(KsT + w*KP + 4*tx);
            float q[4] = {qa4.x, qa4.y, qa4.z, qa4.w};
            float k[4] = {ka4.x, ka4.y, ka4.z, ka4.w};
            #pragma unroll
            for (int ri = 0; ri < 4; ri++)
                #pragma unroll
                for (int rj = 0; rj < 4; rj++)
                    s[ri][rj] += q[ri] * k[rj];
        }
        // Add gathered biases + scale
        #pragma unroll
        for (int ri = 0; ri < 4; ri++) {
            float4 c2 = *(const float4*)(C2Ps + (4*ty + ri)*CP + 4*tx);
            float cc[4] = {c2.x, c2.y, c2.z, c2.w};
            #pragma unroll
            for (int rj = 0; rj < 4; rj++) {
                float p2 = P2Cs[(4*tx + rj)*PP + 4*ty + ri];
                s[ri][rj] = (s[ri][rj] + cc[rj] + p2) * scale;
            }
        }

        // Online softmax (row shared by the 16 tx lanes of this ty)
        #pragma unroll
        for (int ri = 0; ri < 4; ri++) {
            float mx = fmaxf(fmaxf(s[ri][0], s[ri][1]), fmaxf(s[ri][2], s[ri][3]));
            #pragma unroll
            for (int off = 8; off > 0; off >>= 1)
                mx = fmaxf(mx, __shfl_xor_sync(0xffffffffu, mx, off));
            float mnew = fmaxf(m_i[ri], mx);
            float corr = __expf(m_i[ri] - mnew);
            float p0 = __expf(s[ri][0] - mnew);
            float p1 = __expf(s[ri][1] - mnew);
            float p2 = __expf(s[ri][2] - mnew);
            float p3 = __expf(s[ri][3] - mnew);
            float rs = p0 + p1 + p2 + p3;
            #pragma unroll
            for (int off = 8; off > 0; off >>= 1)
                rs += __shfl_xor_sync(0xffffffffu, rs, off);
            l_i[ri] = l_i[ri]*corr + rs;
            m_i[ri] = mnew;
            #pragma unroll
            for (int rw = 0; rw < 4; rw++) o[ri][rw] *= corr;
            float4 pv = {p0, p1, p2, p3};
            *(float4*)(Ss + (4*ty + ri)*SP + 4*tx) = pv;
        }
        __syncthreads();

        // O += P @ V
        #pragma unroll 4
        for (int j = 0; j < 64; j++) {
            float4 vv = *(const float4*)(Vs + j*VP + 4*tx);
            float va[4] = {vv.x, vv.y, vv.z, vv.w};
            float pa[4];
            #pragma unroll
            for (int ri = 0; ri < 4; ri++) pa[ri] = Ss[(4*ty + ri)*SP + j];
            #pragma unroll
            for (int ri = 0; ri < 4; ri++)
                #pragma unroll
                for (int rw = 0; rw < 4; rw++)
                    o[ri][rw] += pa[ri] * va[rw];
        }
    }

    // Write output: out[b][i][h*64 + w]
    #pragma unroll
    for (int ri = 0; ri < 4; ri++) {
        int i = i0 + 4*ty + ri;
        float inv = 1.0f / l_i[ri];
        float4 ov = { o[ri][0]*inv, o[ri][1]*inv, o[ri][2]*inv, o[ri][3]*inv };
        *(float4*)(out + ((size_t)b*SLEN + i)*DD + h*64 + 4*tx) = ov;
    }
}

// ===========================================================================
// Launch
// ===========================================================================
extern "C" void kernel_launch(void* const* d_in, const int* in_sizes, int n_in,
                              void* d_out, int out_size)
{
    (void)in_sizes; (void)n_in; (void)out_size;
    const float* x  = (const float*)d_in[0];
    const float* re = (const float*)d_in[1];
    const float* Wq = (const float*)d_in[2];
    const float* bq = (const float*)d_in[3];
    const float* Wk = (const float*)d_in[4];
    const float* bk = (const float*)d_in[5];
    const float* Wv = (const float*)d_in[6];
    const float* bv = (const float*)d_in[7];
    float* out = (float*)d_out;

    void *qp, *kp, *vp, *pkp, *pqp;
    cudaGetSymbolAddress(&qp,  g_Q);
    cudaGetSymbolAddress(&kp,  g_K);
    cudaGetSymbolAddress(&vp,  g_V);
    cudaGetSymbolAddress(&pkp, g_PK);
    cudaGetSymbolAddress(&pqp, g_PQ);

    cudaFuncSetAttribute(proj_mma_kernel, cudaFuncAttributeMaxDynamicSharedMemorySize,
                         P_SMEM_BYTES);
    cudaFuncSetAttribute(bias_table_kernel, cudaFuncAttributeMaxDynamicSharedMemorySize,
                         T_SMEM_BYTES);
    cudaFuncSetAttribute(attn_kernel, cudaFuncAttributeMaxDynamicSharedMemorySize,
                         ATTN_SMEM_BYTES);

    proj_mma_kernel<<<dim3(40, 24), dim3(256), P_SMEM_BYTES>>>(
        x, re, Wq, bq, Wk, bk, Wv, bv,
        (float*)qp, (float*)kp, (float*)vp, (float*)pkp, (float*)pqp);

    bias_table_kernel<<<dim3(32, 8, 32), dim3(256), T_SMEM_BYTES>>>();

    attn_kernel<<<dim3(4, BB, HH), dim3(512), ATTN_SMEM_BYTES>>>(out);
}

// round 7
// speedup vs baseline: 1.3021x; 1.2265x over previous
#include <cuda_runtime.h>
#include <cuda_bf16.h>
#include <cstdint>

#define SLEN 512
#define BB   8
#define HH   16
#define DD   1024
#define WD   64

// Scratch (device globals — no allocation allowed in kernel_launch)
__device__ float g_Q [HH*BB*SLEN*WD];   // [h][m=b*512+i][w]
__device__ float g_K [HH*BB*SLEN*WD];
__device__ float g_V [HH*BB*SLEN*WD];
__device__ float g_PK[HH*2*SLEN*WD];    // [h][r][w]
__device__ float g_PQ[HH*2*SLEN*WD];
// Bias tables: [h][m(4096)][r(1024)]
__device__ float g_C2P[(size_t)HH*4096*1024];
__device__ float g_P2C[(size_t)HH*4096*1024];

// ===========================================================================
// mma.sync bf16 helpers (sm_80+, compiles for plain sm_100)
// ===========================================================================
__device__ __forceinline__ void mma_bf16(float* d,
    uint32_t a0, uint32_t a1, uint32_t a2, uint32_t a3,
    uint32_t b0, uint32_t b1)
{
    asm volatile(
        "mma.sync.aligned.m16n8k16.row.col.f32.bf16.bf16.f32 "
        "{%0,%1,%2,%3}, {%4,%5,%6,%7}, {%8,%9}, {%0,%1,%2,%3};"
        : "+f"(d[0]), "+f"(d[1]), "+f"(d[2]), "+f"(d[3])
        : "r"(a0), "r"(a1), "r"(a2), "r"(a3), "r"(b0), "r"(b1));
}
__device__ __forceinline__ uint32_t pack_bf16(float a, float b) {
    __nv_bfloat162 h = __floats2bfloat162_rn(a, b);
    return *reinterpret_cast<uint32_t*>(&h);
}
__device__ __forceinline__ float bf16_hi(float a) {
    return __bfloat162float(__float2bfloat16_rn(a));
}
__device__ __forceinline__ float ex2f(float x) {
    float r;
    asm("ex2.approx.f32 %0, %1;" : "=f"(r) : "f"(x));
    return r;
}

// ===========================================================================
// Fused projection GEMM (round-4, known good):
//   C[5120,3072] = [x(4096); re(1024)] @ [Wq|Wk|Wv]^T  (+bias), scatter store.
// ===========================================================================
#define P_PITCH 20
#define P_ARR   (128*P_PITCH)
#define P_SMEM_WORDS (2*4*P_ARR)
#define P_SMEM_BYTES (P_SMEM_WORDS*4)    // 81920

__global__ __launch_bounds__(256, 1) void proj_mma_kernel(
    const float* __restrict__ x, const float* __restrict__ re,
    const float* __restrict__ Wq, const float* __restrict__ bq,
    const float* __restrict__ Wk, const float* __restrict__ bk,
    const float* __restrict__ Wv, const float* __restrict__ bv,
    float* __restrict__ outQ, float* __restrict__ outK, float* __restrict__ outV,
    float* __restrict__ outPK, float* __restrict__ outPQ)
{
    extern __shared__ uint32_t smw[];
    const int m0 = blockIdx.x * 128;
    const int n0 = blockIdx.y * 128;
    const bool isRe = (m0 >= 4096);
    const int nreg = n0 >> 10;
    if (isRe && nreg == 2) return;

    const int tid  = threadIdx.x;
    const int lane = tid & 31;
    const int wid  = tid >> 5;
    const int wm   = wid >> 2;
    const int wn   = wid & 3;

    const float* Ag = isRe ? (re + (size_t)(m0 - 4096) * DD) : (x + (size_t)m0 * DD);
    const float* Wg = ((nreg == 0) ? Wq : (nreg == 1) ? Wk : Wv) + (size_t)(n0 & 1023) * DD;

    const int srow[4] = { tid >> 3, (tid + 256) >> 3, (tid + 512) >> 3, (tid + 768) >> 3 };
    const int sf4  = tid & 7;

    float acc[4][4][4] = {};
    float4 sa[4], sw4[4];

    #pragma unroll
    for (int j = 0; j < 4; j++) {
        sa[j]  = *(const float4*)(Ag + (size_t)srow[j]*DD + sf4*4);
        sw4[j] = *(const float4*)(Wg + (size_t)srow[j]*DD + sf4*4);
    }
    {
        uint32_t* Ah = smw;             uint32_t* Al = smw + P_ARR;
        uint32_t* Wh = smw + 2*P_ARR;   uint32_t* Wl = smw + 3*P_ARR;
        #pragma unroll
        for (int j = 0; j < 4; j++) {
            int wbase = srow[j]*P_PITCH + sf4*2;
            float4 v = sa[j];
            Ah[wbase]   = pack_bf16(v.x, v.y);
            Ah[wbase+1] = pack_bf16(v.z, v.w);
            Al[wbase]   = pack_bf16(v.x - bf16_hi(v.x), v.y - bf16_hi(v.y));
            Al[wbase+1] = pack_bf16(v.z - bf16_hi(v.z), v.w - bf16_hi(v.w));
            v = sw4[j];
            Wh[wbase]   = pack_bf16(v.x, v.y);
            Wh[wbase+1] = pack_bf16(v.z, v.w);
            Wl[wbase]   = pack_bf16(v.x - bf16_hi(v.x), v.y - bf16_hi(v.y));
            Wl[wbase+1] = pack_bf16(v.z - bf16_hi(v.z), v.w - bf16_hi(v.w));
        }
    }
    __syncthreads();

    for (int c = 0; c < 32; c++) {
        const int buf = c & 1;
        if (c + 1 < 32) {
            const int kc = (c + 1) * 32;
            #pragma unroll
            for (int j = 0; j < 4; j++) {
                sa[j]  = *(const float4*)(Ag + (size_t)srow[j]*DD + kc + sf4*4);
                sw4[j] = *(const float4*)(Wg + (size_t)srow[j]*DD + kc + sf4*4);
            }
        }
        {
            const uint32_t* Ah = smw + (buf*4 + 0)*P_ARR;
            const uint32_t* Al = smw + (buf*4 + 1)*P_ARR;
            const uint32_t* Wh = smw + (buf*4 + 2)*P_ARR;
            const uint32_t* Wl = smw + (buf*4 + 3)*P_ARR;
            #pragma unroll
            for (int ks = 0; ks < 2; ks++) {
                const int kw = (lane & 3) + ks*8;
                uint32_t ah[4][4], al[4][4];
                #pragma unroll
                for (int mt = 0; mt < 4; mt++) {
                    int r = wm*64 + mt*16 + (lane >> 2);
                    int b0 = r*P_PITCH + kw;
                    ah[mt][0] = Ah[b0];       ah[mt][1] = Ah[b0 + 8*P_PITCH];
                    ah[mt][2] = Ah[b0 + 4];   ah[mt][3] = Ah[b0 + 8*P_PITCH + 4];
                    al[mt][0] = Al[b0];       al[mt][1] = Al[b0 + 8*P_PITCH];
                    al[mt][2] = Al[b0 + 4];   al[mt][3] = Al[b0 + 8*P_PITCH + 4];
                }
                uint32_t bh[4][2], bl[4][2];
                #pragma unroll
                for (int nt = 0; nt < 4; nt++) {
                    int rn = wn*32 + nt*8 + (lane >> 2);
                    int b0 = rn*P_PITCH + kw;
                    bh[nt][0] = Wh[b0]; bh[nt][1] = Wh[b0 + 4];
                    bl[nt][0] = Wl[b0]; bl[nt][1] = Wl[b0 + 4];
                }
                #pragma unroll
                for (int mt = 0; mt < 4; mt++)
                    #pragma unroll
                    for (int nt = 0; nt < 4; nt++) {
                        mma_bf16(acc[mt][nt], ah[mt][0], ah[mt][1], ah[mt][2], ah[mt][3],
                                 bh[nt][0], bh[nt][1]);
                        mma_bf16(acc[mt][nt], ah[mt][0], ah[mt][1], ah[mt][2], ah[mt][3],
                                 bl[nt][0], bl[nt][1]);
                        mma_bf16(acc[mt][nt], al[mt][0], al[mt][1], al[mt][2], al[mt][3],
                                 bh[nt][0], bh[nt][1]);
                    }
            }
        }
        if (c + 1 < 32) {
            const int ob = 1 - buf;
            uint32_t* Ah = smw + (ob*4 + 0)*P_ARR;
            uint32_t* Al = smw + (ob*4 + 1)*P_ARR;
            uint32_t* Wh = smw + (ob*4 + 2)*P_ARR;
            uint32_t* Wl = smw + (ob*4 + 3)*P_ARR;
            #pragma unroll
            for (int j = 0; j < 4; j++) {
                int wbase = srow[j]*P_PITCH + sf4*2;
                float4 v = sa[j];
                Ah[wbase]   = pack_bf16(v.x, v.y);
                Ah[wbase+1] = pack_bf16(v.z, v.w);
                Al[wbase]   = pack_bf16(v.x - bf16_hi(v.x), v.y - bf16_hi(v.y));
                Al[wbase+1] = pack_bf16(v.z - bf16_hi(v.z), v.w - bf16_hi(v.w));
                v = sw4[j];
                Wh[wbase]   = pack_bf16(v.x, v.y);
                Wh[wbase+1] = pack_bf16(v.z, v.w);
                Wl[wbase]   = pack_bf16(v.x - bf16_hi(v.x), v.y - bf16_hi(v.y));
                Wl[wbase+1] = pack_bf16(v.z - bf16_hi(v.z), v.w - bf16_hi(v.w));
            }
        }
        __syncthreads();
    }

    const float* bp = (nreg == 0) ? bq : (nreg == 1) ? bk : bv;
    float* baseO;
    int Mrows, moff;
    if (!isRe) {
        baseO = (nreg == 0) ? outQ : (nreg == 1) ? outK : outV;
        Mrows = 4096; moff = m0;
    } else {
        baseO = (nreg == 0) ? outPQ : outPK;
        Mrows = 1024; moff = m0 - 4096;
    }

    #pragma unroll
    for (int mt = 0; mt < 4; mt++) {
        int m = moff + wm*64 + mt*16 + (lane >> 2);
        #pragma unroll
        for (int nt = 0; nt < 4; nt++) {
            int ncl = (n0 & 1023) + wn*32 + nt*8 + (lane & 3)*2;
            int hh = ncl >> 6, w = ncl & 63;
            float bx = bp[ncl], by = bp[ncl + 1];
            float* d0 = baseO + ((size_t)hh*Mrows + m)*64 + w;
            float2 v0 = { acc[mt][nt][0] + bx, acc[mt][nt][1] + by };
            float2 v1 = { acc[mt][nt][2] + bx, acc[mt][nt][3] + by };
            *(float2*)d0 = v0;
            *(float2*)(d0 + 8*64) = v1;
        }
    }
}

// ===========================================================================
// Bias table GEMM — SINGLE bf16 product (bias terms are ~50x smaller than
// main scores; 4e-3 relative error here is ~2e-5 on logits).
//   tbl 0: C2P[h,m,r] = Q[h,m,:]·PK[h,r,:];  tbl 1: P2C = K·PQ
// ===========================================================================
#define T_PITCH 36
#define T_ARR   (128*T_PITCH)
#define T_SMEM_BYTES (2*T_ARR*4)         // 36864

__global__ __launch_bounds__(256, 1) void bias_table_kernel()
{
    extern __shared__ uint32_t smw[];
    const int m0 = blockIdx.x * 128;     // [0,4096)
    const int n0 = blockIdx.y * 128;     // [0,1024)
    const int h   = blockIdx.z & 15;
    const int tbl = blockIdx.z >> 4;

    const int tid  = threadIdx.x;
    const int lane = tid & 31;
    const int wid  = tid >> 5;
    const int wm   = wid >> 2;
    const int wn   = wid & 3;

    const float* Ag = (tbl ? g_K : g_Q) + ((size_t)h*4096 + m0) * WD;
    const float* Bg = (tbl ? g_PQ : g_PK) + ((size_t)h*1024 + n0) * WD;
    float* Cg = (tbl ? g_P2C : g_C2P) + (size_t)h*4096*1024;

    uint32_t* Ah = smw;
    uint32_t* Bh = smw + T_ARR;

    #pragma unroll
    for (int v = 0; v < 8; v++) {
        int idx = v*256 + tid;
        int row = idx >> 4;
        int cw  = idx & 15;
        int wbase = row*T_PITCH + cw*2;
        float4 a = *(const float4*)(Ag + (size_t)row*WD + cw*4);
        Ah[wbase]   = pack_bf16(a.x, a.y);
        Ah[wbase+1] = pack_bf16(a.z, a.w);
        float4 b = *(const float4*)(Bg + (size_t)row*WD + cw*4);
        Bh[wbase]   = pack_bf16(b.x, b.y);
        Bh[wbase+1] = pack_bf16(b.z, b.w);
    }
    __syncthreads();

    float acc[4][4][4] = {};
    #pragma unroll
    for (int ks = 0; ks < 4; ks++) {
        const int kw = (lane & 3) + ks*8;
        uint32_t ah[4][4];
        #pragma unroll
        for (int mt = 0; mt < 4; mt++) {
            int r = wm*64 + mt*16 + (lane >> 2);
            int b0 = r*T_PITCH + kw;
            ah[mt][0] = Ah[b0];       ah[mt][1] = Ah[b0 + 8*T_PITCH];
            ah[mt][2] = Ah[b0 + 4];   ah[mt][3] = Ah[b0 + 8*T_PITCH + 4];
        }
        uint32_t bh[4][2];
        #pragma unroll
        for (int nt = 0; nt < 4; nt++) {
            int rn = wn*32 + nt*8 + (lane >> 2);
            int b0 = rn*T_PITCH + kw;
            bh[nt][0] = Bh[b0]; bh[nt][1] = Bh[b0 + 4];
        }
        #pragma unroll
        for (int mt = 0; mt < 4; mt++)
            #pragma unroll
            for (int nt = 0; nt < 4; nt++)
                mma_bf16(acc[mt][nt], ah[mt][0], ah[mt][1], ah[mt][2], ah[mt][3],
                         bh[nt][0], bh[nt][1]);
    }

    #pragma unroll
    for (int mt = 0; mt < 4; mt++) {
        int m = m0 + wm*64 + mt*16 + (lane >> 2);
        #pragma unroll
        for (int nt = 0; nt < 4; nt++) {
            int ncl = n0 + wn*32 + nt*8 + (lane & 3)*2;
            float* d0 = Cg + (size_t)m*1024 + ncl;
            *(float2*)d0 = make_float2(acc[mt][nt][0], acc[mt][nt][1]);
            *(float2*)(d0 + 8*1024) = make_float2(acc[mt][nt][2], acc[mt][nt][3]);
        }
    }
}

// ===========================================================================
// HMMA flash attention. CTA = 128 i-rows (8 warps, m16 each) x full S j-loop
// in 8 tiles of 64. QK^T and PV via split-bf16 mma.sync (3 products each);
// P converts C-frag -> A-frag in registers. Bias tables gathered per tile.
// ===========================================================================
#define AQ_P 36    // word pitch for bf16x2 operand arrays (bank = 4g+t)
#define AB_P 66    // fp32 pitch for C2P tile [di][jl]
#define AP2_P 129  // fp32 pitch for P2C tile [jl][di]
#define W_QH 0
#define W_QL (W_QH + 128*AQ_P)
#define W_KH (W_QL + 128*AQ_P)
#define W_KL (W_KH + 64*AQ_P)
#define W_VH (W_KL + 64*AQ_P)
#define W_VL (W_VH + 64*AQ_P)
#define W_C2 (W_VL + 64*AQ_P)
#define W_P2 (W_C2 + 128*AB_P)
#define ATTN_WORDS (W_P2 + 64*AP2_P)
#define ATTN_SMEM_BYTES (ATTN_WORDS*4)   // 140544

__global__ __launch_bounds__(256, 1) void attn_mma_kernel(float* __restrict__ out)
{
    extern __shared__ uint32_t smw[];
    float* fC2P = (float*)(smw + W_C2);
    float* fP2C = (float*)(smw + W_P2);

    const int h  = blockIdx.z;
    const int b  = blockIdx.y;
    const int i0 = blockIdx.x * 128;
    const int tid  = threadIdx.x;
    const int lane = tid & 31;
    const int warp = tid >> 5;
    const int g = lane >> 2;       // row within m16 half
    const int t = lane & 3;        // col quad index

    const float* Qg  = g_Q + ((size_t)(h*BB + b)*SLEN + i0)*WD;
    const float* Kg  = g_K + (size_t)(h*BB + b)*SLEN*WD;
    const float* Vg  = g_V + (size_t)(h*BB + b)*SLEN*WD;
    const float* C2Pg = g_C2P + ((size_t)h*4096 + (size_t)b*512)*1024;
    const float* P2Cg = g_P2C + ((size_t)h*4096 + (size_t)b*512)*1024;

    // ---- Stage Q (once) as hi/lo bf16x2 ----
    for (int idx = tid; idx < 2048; idx += 256) {
        int r = idx >> 4, c4 = (idx & 15) << 2;
        float4 v = *(const float4*)(Qg + r*WD + c4);
        int wb = r*AQ_P + (c4 >> 1);
        smw[W_QH + wb]     = pack_bf16(v.x, v.y);
        smw[W_QH + wb + 1] = pack_bf16(v.z, v.w);
        smw[W_QL + wb]     = pack_bf16(v.x - bf16_hi(v.x), v.y - bf16_hi(v.y));
        smw[W_QL + wb + 1] = pack_bf16(v.z - bf16_hi(v.z), v.w - bf16_hi(v.w));
    }
    __syncthreads();

    // ---- Cache Q a-fragments for all 4 k-steps ----
    uint32_t qh[4][4], ql[4][4];
    {
        const int r0w = (16*warp + g)*AQ_P;
        const int r1w = (16*warp + g + 8)*AQ_P;
        #pragma unroll
        for (int ks = 0; ks < 4; ks++) {
            int o0 = 8*ks + t;
            qh[ks][0] = smw[W_QH + r0w + o0];     qh[ks][1] = smw[W_QH + r1w + o0];
            qh[ks][2] = smw[W_QH + r0w + o0 + 4]; qh[ks][3] = smw[W_QH + r1w + o0 + 4];
            ql[ks][0] = smw[W_QL + r0w + o0];     ql[ks][1] = smw[W_QL + r1w + o0];
            ql[ks][2] = smw[W_QL + r0w + o0 + 4]; ql[ks][3] = smw[W_QL + r1w + o0 + 4];
        }
    }

    float o[8][4] = {};
    float m0 = -1e30f, m1 = -1e30f, l0 = 0.f, l1 = 0.f;
    const float L2S = rsqrtf(192.0f) * 1.44269504f;   // scale * log2(e)
    const int r0 = 16*warp + g;

    for (int jt = 0; jt < 8; jt++) {
        const int j0 = jt * 64;
        __syncthreads();   // prior tile's smem reads complete

        // K hi/lo [j][w-pairs]
        for (int idx = tid; idx < 1024; idx += 256) {
            int r = idx >> 4, c4 = (idx & 15) << 2;
            float4 v = *(const float4*)(Kg + (j0 + r)*WD + c4);
            int wb = r*AQ_P + (c4 >> 1);
            smw[W_KH + wb]     = pack_bf16(v.x, v.y);
            smw[W_KH + wb + 1] = pack_bf16(v.z, v.w);
            smw[W_KL + wb]     = pack_bf16(v.x - bf16_hi(v.x), v.y - bf16_hi(v.y));
            smw[W_KL + wb + 1] = pack_bf16(v.z - bf16_hi(v.z), v.w - bf16_hi(v.w));
        }
        // V transposed hi/lo [w][j-pairs] (conflict-free stores: lane = j-pair)
        for (int idx = tid; idx < 512; idx += 256) {
            int jp = idx & 31, c4 = (idx >> 5) << 2;
            const float* v0p = Vg + (j0 + 2*jp)*WD + c4;
            float4 a = *(const float4*)v0p;
            float4 c = *(const float4*)(v0p + WD);
            smw[W_VH + (c4+0)*AQ_P + jp] = pack_bf16(a.x, c.x);
            smw[W_VH + (c4+1)*AQ_P + jp] = pack_bf16(a.y, c.y);
            smw[W_VH + (c4+2)*AQ_P + jp] = pack_bf16(a.z, c.z);
            smw[W_VH + (c4+3)*AQ_P + jp] = pack_bf16(a.w, c.w);
            smw[W_VL + (c4+0)*AQ_P + jp] = pack_bf16(a.x - bf16_hi(a.x), c.x - bf16_hi(c.x));
            smw[W_VL + (c4+1)*AQ_P + jp] = pack_bf16(a.y - bf16_hi(a.y), c.y - bf16_hi(c.y));
            smw[W_VL + (c4+2)*AQ_P + jp] = pack_bf16(a.z - bf16_hi(a.z), c.z - bf16_hi(c.z));
            smw[W_VL + (c4+3)*AQ_P + jp] = pack_bf16(a.w - bf16_hi(a.w), c.w - bf16_hi(c.w));
        }
        // C2P gather [di][jl]: reversed-j scalar loads
        for (int idx = tid; idx < 2048; idx += 256) {
            int di = idx >> 4, jg = idx & 15;
            const float* src = C2Pg + (size_t)(i0 + di)*1024 + (i0 + di) - j0 + 511 - 4*jg;
            float* dst = fC2P + di*AB_P + 4*jg;
            dst[0] = src[0]; dst[1] = src[-1]; dst[2] = src[-2]; dst[3] = src[-3];
        }
        // P2C gather [jl][di]: contiguous along di
        for (int idx = tid; idx < 8192; idx += 256) {
            int jl = idx >> 7, di = idx & 127;
            fP2C[jl*AP2_P + di] =
                P2Cg[(size_t)(j0 + jl)*1024 + i0 - j0 - jl + 511 + di];
        }
        __syncthreads();

        // ---- S = Q K^T (split bf16, 3 products) ----
        float s[8][4];
        #pragma unroll
        for (int nt = 0; nt < 8; nt++) {
            float c[4] = {0.f, 0.f, 0.f, 0.f};
            #pragma unroll
            for (int ks = 0; ks < 4; ks++) {
                int kb = (8*nt + g)*AQ_P + 8*ks + t;
                uint32_t bh0 = smw[W_KH + kb], bh1 = smw[W_KH + kb + 4];
                uint32_t bl0 = smw[W_KL + kb], bl1 = smw[W_KL + kb + 4];
                mma_bf16(c, qh[ks][0], qh[ks][1], qh[ks][2], qh[ks][3], bh0, bh1);
                mma_bf16(c, qh[ks][0], qh[ks][1], qh[ks][2], qh[ks][3], bl0, bl1);
                mma_bf16(c, ql[ks][0], ql[ks][1], ql[ks][2], ql[ks][3], bh0, bh1);
            }
            s[nt][0] = c[0]; s[nt][1] = c[1]; s[nt][2] = c[2]; s[nt][3] = c[3];
        }

        // ---- bias add + scale (log2 domain) ----
        #pragma unroll
        for (int nt = 0; nt < 8; nt++) {
            int cb = 8*nt + 2*t;
            float2 cA = *(const float2*)(fC2P + r0*AB_P + cb);
            float2 cB = *(const float2*)(fC2P + (r0+8)*AB_P + cb);
            float pA0 = fP2C[cb*AP2_P + r0],     pA1 = fP2C[(cb+1)*AP2_P + r0];
            float pB0 = fP2C[cb*AP2_P + r0 + 8], pB1 = fP2C[(cb+1)*AP2_P + r0 + 8];
            s[nt][0] = (s[nt][0] + cA.x + pA0) * L2S;
            s[nt][1] = (s[nt][1] + cA.y + pA1) * L2S;
            s[nt][2] = (s[nt][2] + cB.x + pB0) * L2S;
            s[nt][3] = (s[nt][3] + cB.y + pB1) * L2S;
        }

        // ---- online softmax (quad-reduce: lanes xor 1,2 share the row) ----
        float mx0 = -1e30f, mx1 = -1e30f;
        #pragma unroll
        for (int nt = 0; nt < 8; nt++) {
            mx0 = fmaxf(mx0, fmaxf(s[nt][0], s[nt][1]));
            mx1 = fmaxf(mx1, fmaxf(s[nt][2], s[nt][3]));
        }
        mx0 = fmaxf(mx0, __shfl_xor_sync(0xffffffffu, mx0, 1));
        mx0 = fmaxf(mx0, __shfl_xor_sync(0xffffffffu, mx0, 2));
        mx1 = fmaxf(mx1, __shfl_xor_sync(0xffffffffu, mx1, 1));
        mx1 = fmaxf(mx1, __shfl_xor_sync(0xffffffffu, mx1, 2));
        float mn0 = fmaxf(m0, mx0), mn1 = fmaxf(m1, mx1);
        float cr0 = ex2f(m0 - mn0), cr1 = ex2f(m1 - mn1);
        float rs0 = 0.f, rs1 = 0.f;
        #pragma unroll
        for (int nt = 0; nt < 8; nt++) {
            s[nt][0] = ex2f(s[nt][0] - mn0);
            s[nt][1] = ex2f(s[nt][1] - mn0);
            s[nt][2] = ex2f(s[nt][2] - mn1);
            s[nt][3] = ex2f(s[nt][3] - mn1);
            rs0 += s[nt][0] + s[nt][1];
            rs1 += s[nt][2] + s[nt][3];
        }
        rs0 += __shfl_xor_sync(0xffffffffu, rs0, 1);
        rs0 += __shfl_xor_sync(0xffffffffu, rs0, 2);
        rs1 += __shfl_xor_sync(0xffffffffu, rs1, 1);
        rs1 += __shfl_xor_sync(0xffffffffu, rs1, 2);
        l0 = l0*cr0 + rs0;  l1 = l1*cr1 + rs1;
        m0 = mn0;  m1 = mn1;
        #pragma unroll
        for (int nt = 0; nt < 8; nt++) {
            o[nt][0] *= cr0; o[nt][1] *= cr0;
            o[nt][2] *= cr1; o[nt][3] *= cr1;
        }

        // ---- O += P V (P: C-frag -> A-frag in registers; split 3 products) ----
        #pragma unroll
        for (int kt = 0; kt < 4; kt++) {
            float p00 = s[2*kt][0],   p01 = s[2*kt][1];
            float p02 = s[2*kt][2],   p03 = s[2*kt][3];
            float p10 = s[2*kt+1][0], p11 = s[2*kt+1][1];
            float p12 = s[2*kt+1][2], p13 = s[2*kt+1][3];
            uint32_t pa0 = pack_bf16(p00, p01), pa1 = pack_bf16(p02, p03);
            uint32_t pa2 = pack_bf16(p10, p11), pa3 = pack_bf16(p12, p13);
            uint32_t pl0 = pack_bf16(p00 - bf16_hi(p00), p01 - bf16_hi(p01));
            uint32_t pl1 = pack_bf16(p02 - bf16_hi(p02), p03 - bf16_hi(p03));
            uint32_t pl2 = pack_bf16(p10 - bf16_hi(p10), p11 - bf16_hi(p11));
            uint32_t pl3 = pack_bf16(p12 - bf16_hi(p12), p13 - bf16_hi(p13));
            #pragma unroll
            for (int nw = 0; nw < 8; nw++) {
                int vb = (8*nw + g)*AQ_P + 8*kt + t;
                uint32_t vh0 = smw[W_VH + vb], vh1 = smw[W_VH + vb + 4];
                uint32_t vl0 = smw[W_VL + vb], vl1 = smw[W_VL + vb + 4];
                mma_bf16(o[nw], pa0, pa1, pa2, pa3, vh0, vh1);
                mma_bf16(o[nw], pa0, pa1, pa2, pa3, vl0, vl1);
                mma_bf16(o[nw], pl0, pl1, pl2, pl3, vh0, vh1);
            }
        }
    }

    // ---- epilogue ----
    float inv0 = 1.0f / l0, inv1 = 1.0f / l1;
    #pragma unroll
    for (int nw = 0; nw < 8; nw++) {
        int wcol = h*64 + 8*nw + 2*t;
        float* d0 = out + ((size_t)b*SLEN + i0 + r0)*DD + wcol;
        *(float2*)d0 = make_float2(o[nw][0]*inv0, o[nw][1]*inv0);
        *(float2*)(d0 + 8*DD) = make_float2(o[nw][2]*inv1, o[nw][3]*inv1);
    }
}

// ===========================================================================
// Launch
// ===========================================================================
extern "C" void kernel_launch(void* const* d_in, const int* in_sizes, int n_in,
                              void* d_out, int out_size)
{
    (void)in_sizes; (void)n_in; (void)out_size;
    const float* x  = (const float*)d_in[0];
    const float* re = (const float*)d_in[1];
    const float* Wq = (const float*)d_in[2];
    const float* bq = (const float*)d_in[3];
    const float* Wk = (const float*)d_in[4];
    const float* bk = (const float*)d_in[5];
    const float* Wv = (const float*)d_in[6];
    const float* bv = (const float*)d_in[7];
    float* out = (float*)d_out;

    void *qp, *kp, *vp, *pkp, *pqp;
    cudaGetSymbolAddress(&qp,  g_Q);
    cudaGetSymbolAddress(&kp,  g_K);
    cudaGetSymbolAddress(&vp,  g_V);
    cudaGetSymbolAddress(&pkp, g_PK);
    cudaGetSymbolAddress(&pqp, g_PQ);

    cudaFuncSetAttribute(proj_mma_kernel, cudaFuncAttributeMaxDynamicSharedMemorySize,
                         P_SMEM_BYTES);
    cudaFuncSetAttribute(bias_table_kernel, cudaFuncAttributeMaxDynamicSharedMemorySize,
                         T_SMEM_BYTES);
    cudaFuncSetAttribute(attn_mma_kernel, cudaFuncAttributeMaxDynamicSharedMemorySize,
                         ATTN_SMEM_BYTES);

    proj_mma_kernel<<<dim3(40, 24), dim3(256), P_SMEM_BYTES>>>(
        x, re, Wq, bq, Wk, bk, Wv, bv,
        (float*)qp, (float*)kp, (float*)vp, (float*)pkp, (float*)pqp);

    bias_table_kernel<<<dim3(32, 8, 32), dim3(256), T_SMEM_BYTES>>>();

    attn_mma_kernel<<<dim3(4, BB, HH), dim3(256), ATTN_SMEM_BYTES>>>(out);
}

// round 8
// speedup vs baseline: 1.5594x; 1.1976x over previous
#include <cuda_runtime.h>
#include <cuda_bf16.h>
#include <cstdint>

#define SLEN 512
#define BB   8
#define HH   16
#define DD   1024
#define WD   64

// Scratch (device globals — no allocation allowed in kernel_launch)
__device__ float g_Q [HH*BB*SLEN*WD];   // [h][m=b*512+i][w]
__device__ float g_K [HH*BB*SLEN*WD];
__device__ float g_V [HH*BB*SLEN*WD];
__device__ float g_PK[HH*2*SLEN*WD];    // [h][r][w]
__device__ float g_PQ[HH*2*SLEN*WD];
// Bias tables (bf16): [h][m(4096)][r(1024)]
__device__ __nv_bfloat16 g_C2P[(size_t)HH*4096*1024];
__device__ __nv_bfloat16 g_P2C[(size_t)HH*4096*1024];

// ===========================================================================
// mma.sync bf16 helpers (sm_80+, compiles for plain sm_100)
// ===========================================================================
__device__ __forceinline__ void mma_bf16(float* d,
    uint32_t a0, uint32_t a1, uint32_t a2, uint32_t a3,
    uint32_t b0, uint32_t b1)
{
    asm volatile(
        "mma.sync.aligned.m16n8k16.row.col.f32.bf16.bf16.f32 "
        "{%0,%1,%2,%3}, {%4,%5,%6,%7}, {%8,%9}, {%0,%1,%2,%3};"
        : "+f"(d[0]), "+f"(d[1]), "+f"(d[2]), "+f"(d[3])
        : "r"(a0), "r"(a1), "r"(a2), "r"(a3), "r"(b0), "r"(b1));
}
__device__ __forceinline__ uint32_t pack_bf16(float a, float b) {
    __nv_bfloat162 h = __floats2bfloat162_rn(a, b);
    return *reinterpret_cast<uint32_t*>(&h);
}
__device__ __forceinline__ float bf16_hi(float a) {
    return __bfloat162float(__float2bfloat16_rn(a));
}
__device__ __forceinline__ float ex2f(float x) {
    float r;
    asm("ex2.approx.f32 %0, %1;" : "=f"(r) : "f"(x));
    return r;
}

// ===========================================================================
// Fused projection GEMM (known good, at mma.sync ceiling):
//   C[5120,3072] = [x(4096); re(1024)] @ [Wq|Wk|Wv]^T  (+bias), scatter store.
// ===========================================================================
#define P_PITCH 20
#define P_ARR   (128*P_PITCH)
#define P_SMEM_WORDS (2*4*P_ARR)
#define P_SMEM_BYTES (P_SMEM_WORDS*4)    // 81920

__global__ __launch_bounds__(256, 1) void proj_mma_kernel(
    const float* __restrict__ x, const float* __restrict__ re,
    const float* __restrict__ Wq, const float* __restrict__ bq,
    const float* __restrict__ Wk, const float* __restrict__ bk,
    const float* __restrict__ Wv, const float* __restrict__ bv,
    float* __restrict__ outQ, float* __restrict__ outK, float* __restrict__ outV,
    float* __restrict__ outPK, float* __restrict__ outPQ)
{
    extern __shared__ uint32_t smw[];
    const int m0 = blockIdx.x * 128;
    const int n0 = blockIdx.y * 128;
    const bool isRe = (m0 >= 4096);
    const int nreg = n0 >> 10;
    if (isRe && nreg == 2) return;

    const int tid  = threadIdx.x;
    const int lane = tid & 31;
    const int wid  = tid >> 5;
    const int wm   = wid >> 2;
    const int wn   = wid & 3;

    const float* Ag = isRe ? (re + (size_t)(m0 - 4096) * DD) : (x + (size_t)m0 * DD);
    const float* Wg = ((nreg == 0) ? Wq : (nreg == 1) ? Wk : Wv) + (size_t)(n0 & 1023) * DD;

    const int srow[4] = { tid >> 3, (tid + 256) >> 3, (tid + 512) >> 3, (tid + 768) >> 3 };
    const int sf4  = tid & 7;

    float acc[4][4][4] = {};
    float4 sa[4], sw4[4];

    #pragma unroll
    for (int j = 0; j < 4; j++) {
        sa[j]  = *(const float4*)(Ag + (size_t)srow[j]*DD + sf4*4);
        sw4[j] = *(const float4*)(Wg + (size_t)srow[j]*DD + sf4*4);
    }
    {
        uint32_t* Ah = smw;             uint32_t* Al = smw + P_ARR;
        uint32_t* Wh = smw + 2*P_ARR;   uint32_t* Wl = smw + 3*P_ARR;
        #pragma unroll
        for (int j = 0; j < 4; j++) {
            int wbase = srow[j]*P_PITCH + sf4*2;
            float4 v = sa[j];
            Ah[wbase]   = pack_bf16(v.x, v.y);
            Ah[wbase+1] = pack_bf16(v.z, v.w);
            Al[wbase]   = pack_bf16(v.x - bf16_hi(v.x), v.y - bf16_hi(v.y));
            Al[wbase+1] = pack_bf16(v.z - bf16_hi(v.z), v.w - bf16_hi(v.w));
            v = sw4[j];
            Wh[wbase]   = pack_bf16(v.x, v.y);
            Wh[wbase+1] = pack_bf16(v.z, v.w);
            Wl[wbase]   = pack_bf16(v.x - bf16_hi(v.x), v.y - bf16_hi(v.y));
            Wl[wbase+1] = pack_bf16(v.z - bf16_hi(v.z), v.w - bf16_hi(v.w));
        }
    }
    __syncthreads();

    for (int c = 0; c < 32; c++) {
        const int buf = c & 1;
        if (c + 1 < 32) {
            const int kc = (c + 1) * 32;
            #pragma unroll
            for (int j = 0; j < 4; j++) {
                sa[j]  = *(const float4*)(Ag + (size_t)srow[j]*DD + kc + sf4*4);
                sw4[j] = *(const float4*)(Wg + (size_t)srow[j]*DD + kc + sf4*4);
            }
        }
        {
            const uint32_t* Ah = smw + (buf*4 + 0)*P_ARR;
            const uint32_t* Al = smw + (buf*4 + 1)*P_ARR;
            const uint32_t* Wh = smw + (buf*4 + 2)*P_ARR;
            const uint32_t* Wl = smw + (buf*4 + 3)*P_ARR;
            #pragma unroll
            for (int ks = 0; ks < 2; ks++) {
                const int kw = (lane & 3) + ks*8;
                uint32_t ah[4][4], al[4][4];
                #pragma unroll
                for (int mt = 0; mt < 4; mt++) {
                    int r = wm*64 + mt*16 + (lane >> 2);
                    int b0 = r*P_PITCH + kw;
                    ah[mt][0] = Ah[b0];       ah[mt][1] = Ah[b0 + 8*P_PITCH];
                    ah[mt][2] = Ah[b0 + 4];   ah[mt][3] = Ah[b0 + 8*P_PITCH + 4];
                    al[mt][0] = Al[b0];       al[mt][1] = Al[b0 + 8*P_PITCH];
                    al[mt][2] = Al[b0 + 4];   al[mt][3] = Al[b0 + 8*P_PITCH + 4];
                }
                uint32_t bh[4][2], bl[4][2];
                #pragma unroll
                for (int nt = 0; nt < 4; nt++) {
                    int rn = wn*32 + nt*8 + (lane >> 2);
                    int b0 = rn*P_PITCH + kw;
                    bh[nt][0] = Wh[b0]; bh[nt][1] = Wh[b0 + 4];
                    bl[nt][0] = Wl[b0]; bl[nt][1] = Wl[b0 + 4];
                }
                #pragma unroll
                for (int mt = 0; mt < 4; mt++)
                    #pragma unroll
                    for (int nt = 0; nt < 4; nt++) {
                        mma_bf16(acc[mt][nt], ah[mt][0], ah[mt][1], ah[mt][2], ah[mt][3],
                                 bh[nt][0], bh[nt][1]);
                        mma_bf16(acc[mt][nt], ah[mt][0], ah[mt][1], ah[mt][2], ah[mt][3],
                                 bl[nt][0], bl[nt][1]);
                        mma_bf16(acc[mt][nt], al[mt][0], al[mt][1], al[mt][2], al[mt][3],
                                 bh[nt][0], bh[nt][1]);
                    }
            }
        }
        if (c + 1 < 32) {
            const int ob = 1 - buf;
            uint32_t* Ah = smw + (ob*4 + 0)*P_ARR;
            uint32_t* Al = smw + (ob*4 + 1)*P_ARR;
            uint32_t* Wh = smw + (ob*4 + 2)*P_ARR;
            uint32_t* Wl = smw + (ob*4 + 3)*P_ARR;
            #pragma unroll
            for (int j = 0; j < 4; j++) {
                int wbase = srow[j]*P_PITCH + sf4*2;
                float4 v = sa[j];
                Ah[wbase]   = pack_bf16(v.x, v.y);
                Ah[wbase+1] = pack_bf16(v.z, v.w);
                Al[wbase]   = pack_bf16(v.x - bf16_hi(v.x), v.y - bf16_hi(v.y));
                Al[wbase+1] = pack_bf16(v.z - bf16_hi(v.z), v.w - bf16_hi(v.w));
                v = sw4[j];
                Wh[wbase]   = pack_bf16(v.x, v.y);
                Wh[wbase+1] = pack_bf16(v.z, v.w);
                Wl[wbase]   = pack_bf16(v.x - bf16_hi(v.x), v.y - bf16_hi(v.y));
                Wl[wbase+1] = pack_bf16(v.z - bf16_hi(v.z), v.w - bf16_hi(v.w));
            }
        }
        __syncthreads();
    }

    const float* bp = (nreg == 0) ? bq : (nreg == 1) ? bk : bv;
    float* baseO;
    int Mrows, moff;
    if (!isRe) {
        baseO = (nreg == 0) ? outQ : (nreg == 1) ? outK : outV;
        Mrows = 4096; moff = m0;
    } else {
        baseO = (nreg == 0) ? outPQ : outPK;
        Mrows = 1024; moff = m0 - 4096;
    }

    #pragma unroll
    for (int mt = 0; mt < 4; mt++) {
        int m = moff + wm*64 + mt*16 + (lane >> 2);
        #pragma unroll
        for (int nt = 0; nt < 4; nt++) {
            int ncl = (n0 & 1023) + wn*32 + nt*8 + (lane & 3)*2;
            int hh = ncl >> 6, w = ncl & 63;
            float bx = bp[ncl], by = bp[ncl + 1];
            float* d0 = baseO + ((size_t)hh*Mrows + m)*64 + w;
            float2 v0 = { acc[mt][nt][0] + bx, acc[mt][nt][1] + by };
            float2 v1 = { acc[mt][nt][2] + bx, acc[mt][nt][3] + by };
            *(float2*)d0 = v0;
            *(float2*)(d0 + 8*64) = v1;
        }
    }
}

// ===========================================================================
// Bias table GEMM — single bf16 product, bf16 output (halves DRAM traffic).
//   tbl 0: C2P[h,m,r] = Q[h,m,:]·PK[h,r,:];  tbl 1: P2C = K·PQ
// ===========================================================================
#define T_PITCH 36
#define T_ARR   (128*T_PITCH)
#define T_SMEM_BYTES (2*T_ARR*4)         // 36864

__global__ __launch_bounds__(256) void bias_table_kernel()
{
    extern __shared__ uint32_t smw[];
    const int m0 = blockIdx.x * 128;     // [0,4096)
    const int n0 = blockIdx.y * 128;     // [0,1024)
    const int h   = blockIdx.z & 15;
    const int tbl = blockIdx.z >> 4;

    const int tid  = threadIdx.x;
    const int lane = tid & 31;
    const int wid  = tid >> 5;
    const int wm   = wid >> 2;
    const int wn   = wid & 3;

    const float* Ag = (tbl ? g_K : g_Q) + ((size_t)h*4096 + m0) * WD;
    const float* Bg = (tbl ? g_PQ : g_PK) + ((size_t)h*1024 + n0) * WD;
    __nv_bfloat16* Cg = (tbl ? g_P2C : g_C2P) + (size_t)h*4096*1024;

    uint32_t* Ah = smw;
    uint32_t* Bh = smw + T_ARR;

    #pragma unroll
    for (int v = 0; v < 8; v++) {
        int idx = v*256 + tid;
        int row = idx >> 4;
        int cw  = idx & 15;
        int wbase = row*T_PITCH + cw*2;
        float4 a = *(const float4*)(Ag + (size_t)row*WD + cw*4);
        Ah[wbase]   = pack_bf16(a.x, a.y);
        Ah[wbase+1] = pack_bf16(a.z, a.w);
        float4 b = *(const float4*)(Bg + (size_t)row*WD + cw*4);
        Bh[wbase]   = pack_bf16(b.x, b.y);
        Bh[wbase+1] = pack_bf16(b.z, b.w);
    }
    __syncthreads();

    float acc[4][4][4] = {};
    #pragma unroll
    for (int ks = 0; ks < 4; ks++) {
        const int kw = (lane & 3) + ks*8;
        uint32_t ah[4][4];
        #pragma unroll
        for (int mt = 0; mt < 4; mt++) {
            int r = wm*64 + mt*16 + (lane >> 2);
            int b0 = r*T_PITCH + kw;
            ah[mt][0] = Ah[b0];       ah[mt][1] = Ah[b0 + 8*T_PITCH];
            ah[mt][2] = Ah[b0 + 4];   ah[mt][3] = Ah[b0 + 8*T_PITCH + 4];
        }
        uint32_t bh[4][2];
        #pragma unroll
        for (int nt = 0; nt < 4; nt++) {
            int rn = wn*32 + nt*8 + (lane >> 2);
            int b0 = rn*T_PITCH + kw;
            bh[nt][0] = Bh[b0]; bh[nt][1] = Bh[b0 + 4];
        }
        #pragma unroll
        for (int mt = 0; mt < 4; mt++)
            #pragma unroll
            for (int nt = 0; nt < 4; nt++)
                mma_bf16(acc[mt][nt], ah[mt][0], ah[mt][1], ah[mt][2], ah[mt][3],
                         bh[nt][0], bh[nt][1]);
    }

    #pragma unroll
    for (int mt = 0; mt < 4; mt++) {
        int m = m0 + wm*64 + mt*16 + (lane >> 2);
        #pragma unroll
        for (int nt = 0; nt < 4; nt++) {
            int ncl = n0 + wn*32 + nt*8 + (lane & 3)*2;
            __nv_bfloat16* d0 = Cg + (size_t)m*1024 + ncl;
            *(uint32_t*)d0 = pack_bf16(acc[mt][nt][0], acc[mt][nt][1]);
            *(uint32_t*)(d0 + 8*1024) = pack_bf16(acc[mt][nt][2], acc[mt][nt][3]);
        }
    }
}

// ===========================================================================
// HMMA flash attention, occupancy-3 version.
// CTA = 64 i-rows (4 warps, m16 each), 128 threads, smem 70.7 KB.
// Q-staging region aliased over the bias tiles (Q frags cached in regs first).
// ===========================================================================
#define AQ_P 36
#define CP_P 66
#define W_KH 0
#define W_KL (W_KH + 64*AQ_P)            // 2304
#define W_VH (W_KL + 64*AQ_P)            // 4608
#define W_VL (W_VH + 64*AQ_P)            // 6912
#define W_C2 (W_VL + 64*AQ_P)            // 9216  (fp32 [di][jl] pitch 66)
#define W_P2 (W_C2 + 64*CP_P)            // 13440 (fp32 [jl][di] pitch 66)
#define ATTN_WORDS (W_P2 + 64*CP_P)      // 17664
#define ATTN_SMEM_BYTES (ATTN_WORDS*4)   // 70656
#define W_QH W_C2
#define W_QL (W_C2 + 64*AQ_P)

__global__ __launch_bounds__(128, 3) void attn_mma_kernel(float* __restrict__ out)
{
    extern __shared__ uint32_t smw[];
    float* fC2P = (float*)(smw + W_C2);
    float* fP2C = (float*)(smw + W_P2);

    const int h  = blockIdx.z;
    const int b  = blockIdx.y;
    const int i0 = blockIdx.x * 64;
    const int tid  = threadIdx.x;
    const int lane = tid & 31;
    const int warp = tid >> 5;     // 0..3
    const int g = lane >> 2;       // row within m16 half
    const int t = lane & 3;        // col quad index

    const float* Qg  = g_Q + ((size_t)(h*BB + b)*SLEN + i0)*WD;
    const float* Kg  = g_K + (size_t)(h*BB + b)*SLEN*WD;
    const float* Vg  = g_V + (size_t)(h*BB + b)*SLEN*WD;
    const __nv_bfloat16* C2Pg = g_C2P + ((size_t)h*4096 + (size_t)b*512)*1024;
    const __nv_bfloat16* P2Cg = g_P2C + ((size_t)h*4096 + (size_t)b*512)*1024;

    // ---- Stage Q (aliased region) and cache a-fragments ----
    for (int idx = tid; idx < 1024; idx += 128) {
        int r = idx >> 4, c4 = (idx & 15) << 2;
        float4 v = *(const float4*)(Qg + r*WD + c4);
        int wb = r*AQ_P + (c4 >> 1);
        smw[W_QH + wb]     = pack_bf16(v.x, v.y);
        smw[W_QH + wb + 1] = pack_bf16(v.z, v.w);
        smw[W_QL + wb]     = pack_bf16(v.x - bf16_hi(v.x), v.y - bf16_hi(v.y));
        smw[W_QL + wb + 1] = pack_bf16(v.z - bf16_hi(v.z), v.w - bf16_hi(v.w));
    }
    __syncthreads();

    uint32_t qh[4][4], ql[4][4];
    {
        const int r0w = (16*warp + g)*AQ_P;
        const int r1w = (16*warp + g + 8)*AQ_P;
        #pragma unroll
        for (int ks = 0; ks < 4; ks++) {
            int o0 = 8*ks + t;
            qh[ks][0] = smw[W_QH + r0w + o0];     qh[ks][1] = smw[W_QH + r1w + o0];
            qh[ks][2] = smw[W_QH + r0w + o0 + 4]; qh[ks][3] = smw[W_QH + r1w + o0 + 4];
            ql[ks][0] = smw[W_QL + r0w + o0];     ql[ks][1] = smw[W_QL + r1w + o0];
            ql[ks][2] = smw[W_QL + r0w + o0 + 4]; ql[ks][3] = smw[W_QL + r1w + o0 + 4];
        }
    }

    float o[8][4] = {};
    float m0 = -1e30f, m1 = -1e30f, l0 = 0.f, l1 = 0.f;
    const float L2S = rsqrtf(192.0f) * 1.44269504f;
    const int r0 = 16*warp + g;

    for (int jt = 0; jt < 8; jt++) {
        const int j0 = jt * 64;
        __syncthreads();   // prior tile reads complete (covers Q frag load at jt=0)

        // K hi/lo [j][w-pairs]
        for (int idx = tid; idx < 1024; idx += 128) {
            int r = idx >> 4, c4 = (idx & 15) << 2;
            float4 v = *(const float4*)(Kg + (j0 + r)*WD + c4);
            int wb = r*AQ_P + (c4 >> 1);
            smw[W_KH + wb]     = pack_bf16(v.x, v.y);
            smw[W_KH + wb + 1] = pack_bf16(v.z, v.w);
            smw[W_KL + wb]     = pack_bf16(v.x - bf16_hi(v.x), v.y - bf16_hi(v.y));
            smw[W_KL + wb + 1] = pack_bf16(v.z - bf16_hi(v.z), v.w - bf16_hi(v.w));
        }
        // V transposed hi/lo [w][j-pairs]
        for (int idx = tid; idx < 512; idx += 128) {
            int jp = idx & 31, c4 = (idx >> 5) << 2;
            const float* v0p = Vg + (j0 + 2*jp)*WD + c4;
            float4 a = *(const float4*)v0p;
            float4 c = *(const float4*)(v0p + WD);
            smw[W_VH + (c4+0)*AQ_P + jp] = pack_bf16(a.x, c.x);
            smw[W_VH + (c4+1)*AQ_P + jp] = pack_bf16(a.y, c.y);
            smw[W_VH + (c4+2)*AQ_P + jp] = pack_bf16(a.z, c.z);
            smw[W_VH + (c4+3)*AQ_P + jp] = pack_bf16(a.w, c.w);
            smw[W_VL + (c4+0)*AQ_P + jp] = pack_bf16(a.x - bf16_hi(a.x), c.x - bf16_hi(c.x));
            smw[W_VL + (c4+1)*AQ_P + jp] = pack_bf16(a.y - bf16_hi(a.y), c.y - bf16_hi(c.y));
            smw[W_VL + (c4+2)*AQ_P + jp] = pack_bf16(a.z - bf16_hi(a.z), c.z - bf16_hi(c.z));
            smw[W_VL + (c4+3)*AQ_P + jp] = pack_bf16(a.w - bf16_hi(a.w), c.w - bf16_hi(c.w));
        }
        // C2P gather [di][jl] (reversed-j bf16 reads)
        for (int idx = tid; idx < 1024; idx += 128) {
            int di = idx >> 4, jg = idx & 15;
            const __nv_bfloat16* src = C2Pg + (size_t)(i0 + di)*1024
                                       + (i0 + di) - j0 + 511 - 4*jg;
            float* dst = fC2P + di*CP_P + 4*jg;
            dst[0] = __bfloat162float(src[0]);
            dst[1] = __bfloat162float(src[-1]);
            dst[2] = __bfloat162float(src[-2]);
            dst[3] = __bfloat162float(src[-3]);
        }
        // P2C gather [jl][di] (contiguous along di)
        for (int idx = tid; idx < 4096; idx += 128) {
            int jl = idx >> 6, di = idx & 63;
            fP2C[jl*CP_P + di] = __bfloat162float(
                P2Cg[(size_t)(j0 + jl)*1024 + i0 - j0 - jl + 511 + di]);
        }
        __syncthreads();

        // ---- S = Q K^T (split bf16, 3 products) ----
        float s[8][4];
        #pragma unroll
        for (int nt = 0; nt < 8; nt++) {
            float c[4] = {0.f, 0.f, 0.f, 0.f};
            #pragma unroll
            for (int ks = 0; ks < 4; ks++) {
                int kb = (8*nt + g)*AQ_P + 8*ks + t;
                uint32_t bh0 = smw[W_KH + kb], bh1 = smw[W_KH + kb + 4];
                uint32_t bl0 = smw[W_KL + kb], bl1 = smw[W_KL + kb + 4];
                mma_bf16(c, qh[ks][0], qh[ks][1], qh[ks][2], qh[ks][3], bh0, bh1);
                mma_bf16(c, qh[ks][0], qh[ks][1], qh[ks][2], qh[ks][3], bl0, bl1);
                mma_bf16(c, ql[ks][0], ql[ks][1], ql[ks][2], ql[ks][3], bh0, bh1);
            }
            s[nt][0] = c[0]; s[nt][1] = c[1]; s[nt][2] = c[2]; s[nt][3] = c[3];
        }

        // ---- bias add + scale (log2 domain) ----
        #pragma unroll
        for (int nt = 0; nt < 8; nt++) {
            int cb = 8*nt + 2*t;
            float2 cA = *(const float2*)(fC2P + r0*CP_P + cb);
            float2 cB = *(const float2*)(fC2P + (r0+8)*CP_P + cb);
            float pA0 = fP2C[cb*CP_P + r0],     pA1 = fP2C[(cb+1)*CP_P + r0];
            float pB0 = fP2C[cb*CP_P + r0 + 8], pB1 = fP2C[(cb+1)*CP_P + r0 + 8];
            s[nt][0] = (s[nt][0] + cA.x + pA0) * L2S;
            s[nt][1] = (s[nt][1] + cA.y + pA1) * L2S;
            s[nt][2] = (s[nt][2] + cB.x + pB0) * L2S;
            s[nt][3] = (s[nt][3] + cB.y + pB1) * L2S;
        }

        // ---- online softmax (quad reduce) ----
        float mx0 = -1e30f, mx1 = -1e30f;
        #pragma unroll
        for (int nt = 0; nt < 8; nt++) {
            mx0 = fmaxf(mx0, fmaxf(s[nt][0], s[nt][1]));
            mx1 = fmaxf(mx1, fmaxf(s[nt][2], s[nt][3]));
        }
        mx0 = fmaxf(mx0, __shfl_xor_sync(0xffffffffu, mx0, 1));
        mx0 = fmaxf(mx0, __shfl_xor_sync(0xffffffffu, mx0, 2));
        mx1 = fmaxf(mx1, __shfl_xor_sync(0xffffffffu, mx1, 1));
        mx1 = fmaxf(mx1, __shfl_xor_sync(0xffffffffu, mx1, 2));
        float mn0 = fmaxf(m0, mx0), mn1 = fmaxf(m1, mx1);
        float cr0 = ex2f(m0 - mn0), cr1 = ex2f(m1 - mn1);
        float rs0 = 0.f, rs1 = 0.f;
        #pragma unroll
        for (int nt = 0; nt < 8; nt++) {
            s[nt][0] = ex2f(s[nt][0] - mn0);
            s[nt][1] = ex2f(s[nt][1] - mn0);
            s[nt][2] = ex2f(s[nt][2] - mn1);
            s[nt][3] = ex2f(s[nt][3] - mn1);
            rs0 += s[nt][0] + s[nt][1];
            rs1 += s[nt][2] + s[nt][3];
        }
        rs0 += __shfl_xor_sync(0xffffffffu, rs0, 1);
        rs0 += __shfl_xor_sync(0xffffffffu, rs0, 2);
        rs1 += __shfl_xor_sync(0xffffffffu, rs1, 1);
        rs1 += __shfl_xor_sync(0xffffffffu, rs1, 2);
        l0 = l0*cr0 + rs0;  l1 = l1*cr1 + rs1;
        m0 = mn0;  m1 = mn1;
        #pragma unroll
        for (int nt = 0; nt < 8; nt++) {
            o[nt][0] *= cr0; o[nt][1] *= cr0;
            o[nt][2] *= cr1; o[nt][3] *= cr1;
        }

        // ---- O += P V (C-frag -> A-frag in registers, 3 products) ----
        #pragma unroll
        for (int kt = 0; kt < 4; kt++) {
            float p00 = s[2*kt][0],   p01 = s[2*kt][1];
            float p02 = s[2*kt][2],   p03 = s[2*kt][3];
            float p10 = s[2*kt+1][0], p11 = s[2*kt+1][1];
            float p12 = s[2*kt+1][2], p13 = s[2*kt+1][3];
            uint32_t pa0 = pack_bf16(p00, p01), pa1 = pack_bf16(p02, p03);
            uint32_t pa2 = pack_bf16(p10, p11), pa3 = pack_bf16(p12, p13);
            uint32_t pl0 = pack_bf16(p00 - bf16_hi(p00), p01 - bf16_hi(p01));
            uint32_t pl1 = pack_bf16(p02 - bf16_hi(p02), p03 - bf16_hi(p03));
            uint32_t pl2 = pack_bf16(p10 - bf16_hi(p10), p11 - bf16_hi(p11));
            uint32_t pl3 = pack_bf16(p12 - bf16_hi(p12), p13 - bf16_hi(p13));
            #pragma unroll
            for (int nw = 0; nw < 8; nw++) {
                int vb = (8*nw + g)*AQ_P + 8*kt + t;
                uint32_t vh0 = smw[W_VH + vb], vh1 = smw[W_VH + vb + 4];
                uint32_t vl0 = smw[W_VL + vb], vl1 = smw[W_VL + vb + 4];
                mma_bf16(o[nw], pa0, pa1, pa2, pa3, vh0, vh1);
                mma_bf16(o[nw], pa0, pa1, pa2, pa3, vl0, vl1);
                mma_bf16(o[nw], pl0, pl1, pl2, pl3, vh0, vh1);
            }
        }
    }

    // ---- epilogue ----
    float inv0 = 1.0f / l0, inv1 = 1.0f / l1;
    #pragma unroll
    for (int nw = 0; nw < 8; nw++) {
        int wcol = h*64 + 8*nw + 2*t;
        float* d0 = out + ((size_t)b*SLEN + i0 + r0)*DD + wcol;
        *(float2*)d0 = make_float2(o[nw][0]*inv0, o[nw][1]*inv0);
        *(float2*)(d0 + 8*DD) = make_float2(o[nw][2]*inv1, o[nw][3]*inv1);
    }
}

// ===========================================================================
// Launch
// ===========================================================================
extern "C" void kernel_launch(void* const* d_in, const int* in_sizes, int n_in,
                              void* d_out, int out_size)
{
    (void)in_sizes; (void)n_in; (void)out_size;
    const float* x  = (const float*)d_in[0];
    const float* re = (const float*)d_in[1];
    const float* Wq = (const float*)d_in[2];
    const float* bq = (const float*)d_in[3];
    const float* Wk = (const float*)d_in[4];
    const float* bk = (const float*)d_in[5];
    const float* Wv = (const float*)d_in[6];
    const float* bv = (const float*)d_in[7];
    float* out = (float*)d_out;

    void *qp, *kp, *vp, *pkp, *pqp;
    cudaGetSymbolAddress(&qp,  g_Q);
    cudaGetSymbolAddress(&kp,  g_K);
    cudaGetSymbolAddress(&vp,  g_V);
    cudaGetSymbolAddress(&pkp, g_PK);
    cudaGetSymbolAddress(&pqp, g_PQ);

    cudaFuncSetAttribute(proj_mma_kernel, cudaFuncAttributeMaxDynamicSharedMemorySize,
                         P_SMEM_BYTES);
    cudaFuncSetAttribute(bias_table_kernel, cudaFuncAttributeMaxDynamicSharedMemorySize,
                         T_SMEM_BYTES);
    cudaFuncSetAttribute(attn_mma_kernel, cudaFuncAttributeMaxDynamicSharedMemorySize,
                         ATTN_SMEM_BYTES);

    proj_mma_kernel<<<dim3(40, 24), dim3(256), P_SMEM_BYTES>>>(
        x, re, Wq, bq, Wk, bk, Wv, bv,
        (float*)qp, (float*)kp, (float*)vp, (float*)pkp, (float*)pqp);

    bias_table_kernel<<<dim3(32, 8, 32), dim3(256), T_SMEM_BYTES>>>();

    attn_mma_kernel<<<dim3(8, BB, HH), dim3(128), ATTN_SMEM_BYTES>>>(out);
}